// round 9
// baseline (speedup 1.0000x reference)
#include <cuda_runtime.h>
#include <math.h>
#include <cstdint>

#define MAXN 100000
#define MAXE 1600000
#define NBLK 98
typedef unsigned long long u64;

__device__ __forceinline__ float tf32_hi(float x){return __uint_as_float(__float_as_uint(x)&0xffffe000u);}

// m16n8k8 tf32 mma (sm_80+ PTX)
__device__ __forceinline__ void mma8(float* c,const uint32_t* a,uint32_t b0,uint32_t b1){
    asm volatile("mma.sync.aligned.m16n8k8.row.col.f32.tf32.tf32.f32 "
                 "{%0,%1,%2,%3},{%4,%5,%6,%7},{%8,%9},{%0,%1,%2,%3};"
        :"+f"(c[0]),"+f"(c[1]),"+f"(c[2]),"+f"(c[3])
        :"r"(a[0]),"r"(a[1]),"r"(a[2]),"r"(a[3]),"r"(b0),"r"(b1));
}

__device__ float  g_h[(size_t)MAXN*128];
__device__ float  g_agg[(size_t)MAXN*128];
__device__ float  g_g1[MAXE];
__device__ float  g_g2[MAXE];
__device__ float  g_d1[MAXN];
__device__ float  g_d2[MAXN];
__device__ int    g_cnt[MAXN];
__device__ int    g_cur[MAXN];
__device__ int    g_base[MAXN];
__device__ int    g_bsums[NBLK+1];
__device__ float4 g_edges[MAXE];

__global__ void init_kernel(float*d1,float*d2,int*cur,int n){
    int i=blockIdx.x*blockDim.x+threadIdx.x;
    if(i<n){d1[i]=1.0f;d2[i]=1.0f;cur[i]=0;}
}
__global__ void zero_cnt_kernel(int*cnt,int n){
    int i=blockIdx.x*blockDim.x+threadIdx.x;
    if(i<n) cnt[i]=0;
}
__global__ void hist_kernel(const int* __restrict__ cols,int* __restrict__ cnt,int E){
    int e=blockIdx.x*blockDim.x+threadIdx.x;
    if(e<E) atomicAdd(cnt+__ldg(cols+e),1);
}

// ---------------------------------------------------------------------------
// Tensor-core gate: split-fp32 tf32, K=48, bias in C-init. (cnt moved out)
__global__ void __launch_bounds__(256) gate_mma_kernel(
    const float* __restrict__ ea,
    const float* __restrict__ m1w1,const float* __restrict__ m1b1,
    const float* __restrict__ m1w2,const float* __restrict__ m1b2,
    const float* __restrict__ m2w1,const float* __restrict__ m2b1,
    const float* __restrict__ m2w2,const float* __restrict__ m2b2,
    const int* __restrict__ cols,
    float* __restrict__ g1,float* __restrict__ g2,
    float* __restrict__ deg1,float* __restrict__ deg2,int E)
{
    extern __shared__ float ds[];
    float* biasp=ds+2*48*136;
    float* w2p  =biasp+256;
    int tid=threadIdx.x;

    for(int idx=tid;idx<2*48*128;idx+=256){
        int layer=idx/6144,rem=idx%6144,k=rem>>7,n=rem&127;
        const float* W=layer?m2w1:m1w1;
        float v;
        if(k<16)      v=tf32_hi(__ldg(W+k*128+n));
        else if(k<32) v=tf32_hi(__ldg(W+(k-16)*128+n));
        else          {float w=__ldg(W+(k-32)*128+n);v=w-tf32_hi(w);}
        ds[layer*6528+k*136+n]=v;
    }
    if(tid<256){
        biasp[tid]=(tid<128)?__ldg(m1b1+tid):__ldg(m2b1+tid-128);
        w2p[tid]  =(tid<128)?__ldg(m1w2+tid):__ldg(m2w2+tid-128);
    }
    __syncthreads();

    int lane=tid&31,g=lane>>2,t=lane&3;
    int w=blockIdx.x*(blockDim.x>>5)+(tid>>5);
    int nwarps=gridDim.x*(blockDim.x>>5);
    int ntask=(E+63)>>6;
    float b2v[2]={__ldg(m1b2),__ldg(m2b2)};

    for(int task=w;task<ntask;task+=nwarps){
        int e0=task*64;
        uint32_t Ahi[4][8],Alo[4][8];
        #pragma unroll
        for(int mt=0;mt<4;mt++){
            int r1=e0+mt*16+g,r2=r1+8;
            #pragma unroll
            for(int j=0;j<4;j++){
                int ac=(j&1)*4+(j>>1)*8+t;
                int fi=(j>>1)*4+(j&1)*2;
                float v1=(r1<E)?__ldg(ea+(size_t)r1*16+ac):0.f;
                float v2=(r2<E)?__ldg(ea+(size_t)r2*16+ac):0.f;
                uint32_t h1=__float_as_uint(v1)&0xffffe000u;
                uint32_t h2=__float_as_uint(v2)&0xffffe000u;
                Ahi[mt][fi]=h1;  Ahi[mt][fi+1]=h2;
                Alo[mt][fi]=__float_as_uint(v1-__uint_as_float(h1));
                Alo[mt][fi+1]=__float_as_uint(v2-__uint_as_float(h2));
            }
        }
        #pragma unroll
        for(int layer=0;layer<2;layer++){
            const float* Bl=ds+layer*6528;
            const float* biasl=biasp+layer*128;
            const float* w2l=w2p+layer*128;
            float p0[4]={0,0,0,0},p1[4]={0,0,0,0};
            #pragma unroll 1
            for(int nt=0;nt<16;nt++){
                int n0=nt*8;
                float bA=biasl[n0+2*t],bB=biasl[n0+2*t+1];
                float c[4][4];
                #pragma unroll
                for(int mt=0;mt<4;mt++){c[mt][0]=bA;c[mt][1]=bB;c[mt][2]=bA;c[mt][3]=bB;}
                #define STEP(AARR,OFF,K0) do{                                   \
                    uint32_t b0=__float_as_uint(Bl[(K0+t)*136+n0+g]);           \
                    uint32_t b1v=__float_as_uint(Bl[(K0+t+4)*136+n0+g]);        \
                    _Pragma("unroll")                                           \
                    for(int mt=0;mt<4;mt++) mma8(c[mt],&AARR[mt][OFF],b0,b1v);  \
                }while(0)
                STEP(Ahi,0,0);  STEP(Ahi,4,8);
                STEP(Alo,0,16); STEP(Alo,4,24);
                STEP(Ahi,0,32); STEP(Ahi,4,40);
                #undef STEP
                float wA=w2l[n0+2*t],wB=w2l[n0+2*t+1];
                #pragma unroll
                for(int mt=0;mt<4;mt++){
                    p0[mt]+=fmaxf(c[mt][0],0.f)*wA+fmaxf(c[mt][1],0.f)*wB;
                    p1[mt]+=fmaxf(c[mt][2],0.f)*wA+fmaxf(c[mt][3],0.f)*wB;
                }
            }
            #pragma unroll
            for(int mt=0;mt<4;mt++){
                p0[mt]+=__shfl_xor_sync(0xffffffffu,p0[mt],1);
                p0[mt]+=__shfl_xor_sync(0xffffffffu,p0[mt],2);
                p1[mt]+=__shfl_xor_sync(0xffffffffu,p1[mt],1);
                p1[mt]+=__shfl_xor_sync(0xffffffffu,p1[mt],2);
            }
            if(t==0){
                float b2=b2v[layer];
                #pragma unroll
                for(int mt=0;mt<4;mt++){
                    int e=e0+mt*16+g;
                    if(e<E){
                        float gg=1.0f/(1.0f+expf(-(p0[mt]+b2)));
                        int c_=__ldg(cols+e);
                        if(layer==0){g1[e]=gg;atomicAdd(deg1+c_,gg);}
                        else        {g2[e]=gg;atomicAdd(deg2+c_,gg);}
                    }
                    int e2=e0+mt*16+g+8;
                    if(e2<E){
                        float gg=1.0f/(1.0f+expf(-(p1[mt]+b2)));
                        int c_=__ldg(cols+e2);
                        if(layer==0){g1[e2]=gg;atomicAdd(deg1+c_,gg);}
                        else        {g2[e2]=gg;atomicAdd(deg2+c_,gg);}
                    }
                }
            }
        }
    }
}

// ---------------------------------------------------------------------------
// Dense GEMM via mma.sync tf32 split-fp32 (unchanged from R8).
__global__ void __launch_bounds__(256) gemm_mma_kernel(
    const float* __restrict__ X,const float* __restrict__ W,
    float* __restrict__ out,int n,int relu_in)
{
    extern __shared__ float sm[];
    float* Ws=sm;                 // 128*136
    float* Xs=sm+128*136;         // 8 warps * 16*132
    int tid=threadIdx.x,wid=tid>>5,lane=tid&31;
    int g=lane>>2,t=lane&3;

    for(int idx=tid;idx<128*32;idx+=256){
        int k=idx>>5,nn=(idx&31)*4;
        float4 v=__ldg((const float4*)(W+k*128+nn));
        float* d=Ws+k*136+nn;
        d[0]=v.x;d[1]=v.y;d[2]=v.z;d[3]=v.w;
    }
    __syncthreads();

    float* Xw=Xs+wid*(16*132);
    int ntiles=(n+127)>>7;
    for(int tile=blockIdx.x;tile<ntiles;tile+=gridDim.x){
        int r0=tile*128+wid*16;
        #pragma unroll 4
        for(int i=0;i<16;i++){
            int r=r0+i;
            float4 v=make_float4(0.f,0.f,0.f,0.f);
            if(r<n) v=__ldg((const float4*)(X+(size_t)r*128)+lane);
            if(relu_in){v.x=fmaxf(v.x,0.f);v.y=fmaxf(v.y,0.f);v.z=fmaxf(v.z,0.f);v.w=fmaxf(v.w,0.f);}
            float* d=Xw+i*132+lane*4;
            d[0]=v.x;d[1]=v.y;d[2]=v.z;d[3]=v.w;
        }
        __syncwarp();

        float c[16][4];
        #pragma unroll
        for(int nf=0;nf<16;nf++){c[nf][0]=0.f;c[nf][1]=0.f;c[nf][2]=0.f;c[nf][3]=0.f;}

        #pragma unroll 1
        for(int ks=0;ks<16;ks++){
            int k0=ks*8;
            float x0=Xw[g*132+k0+t],x1=Xw[(g+8)*132+k0+t];
            float x2=Xw[g*132+k0+t+4],x3=Xw[(g+8)*132+k0+t+4];
            uint32_t ahi[4],alo[4];
            ahi[0]=__float_as_uint(x0)&0xffffe000u; alo[0]=__float_as_uint(x0-__uint_as_float(ahi[0]));
            ahi[1]=__float_as_uint(x1)&0xffffe000u; alo[1]=__float_as_uint(x1-__uint_as_float(ahi[1]));
            ahi[2]=__float_as_uint(x2)&0xffffe000u; alo[2]=__float_as_uint(x2-__uint_as_float(ahi[2]));
            ahi[3]=__float_as_uint(x3)&0xffffe000u; alo[3]=__float_as_uint(x3-__uint_as_float(ahi[3]));
            #pragma unroll
            for(int nf=0;nf<16;nf++){
                int n0=nf*8;
                float b0r=Ws[(k0+t)*136+n0+g],b1r=Ws[(k0+t+4)*136+n0+g];
                uint32_t bh0=__float_as_uint(b0r)&0xffffe000u;
                uint32_t bh1=__float_as_uint(b1r)&0xffffe000u;
                uint32_t bl0=__float_as_uint(b0r-__uint_as_float(bh0));
                uint32_t bl1=__float_as_uint(b1r-__uint_as_float(bh1));
                mma8(c[nf],ahi,bh0,bh1);
                mma8(c[nf],alo,bh0,bh1);
                mma8(c[nf],ahi,bl0,bl1);
            }
        }

        int ra=r0+g,rb=r0+g+8;
        #pragma unroll
        for(int nf=0;nf<16;nf++){
            int col=nf*8+2*t;
            if(ra<n) *(float2*)(out+(size_t)ra*128+col)=make_float2(c[nf][0],c[nf][1]);
            if(rb<n) *(float2*)(out+(size_t)rb*128+col)=make_float2(c[nf][2],c[nf][3]);
        }
        __syncwarp();
    }
}

__global__ void rsqrt_kernel(float*d1,float*d2,int n){
    int i=blockIdx.x*blockDim.x+threadIdx.x;
    if(i<n){d1[i]=rsqrtf(d1[i]);d2[i]=rsqrtf(d2[i]);}
}

__global__ void scan_block_sums(const int* __restrict__ cnt,int* __restrict__ bsums,int n){
    __shared__ int wsum[32];
    int i=blockIdx.x*1024+threadIdx.x;
    int v=(i<n)?cnt[i]:0;
    #pragma unroll
    for(int o=16;o;o>>=1) v+=__shfl_down_sync(0xffffffffu,v,o);
    if((threadIdx.x&31)==0) wsum[threadIdx.x>>5]=v;
    __syncthreads();
    if(threadIdx.x<32){
        int s=wsum[threadIdx.x];
        #pragma unroll
        for(int o=16;o;o>>=1) s+=__shfl_down_sync(0xffffffffu,s,o);
        if(threadIdx.x==0) bsums[blockIdx.x]=s;
    }
}
__global__ void scan_bsums_excl(int*bsums,int nb){
    if(threadIdx.x==0&&blockIdx.x==0){
        int acc=0;
        for(int i=0;i<nb;i++){int t=bsums[i];bsums[i]=acc;acc+=t;}
    }
}
__global__ void scan_final(const int* __restrict__ cnt,const int* __restrict__ bsums,
                           int* __restrict__ base,int n){
    __shared__ int wsum[32];
    int i=blockIdx.x*1024+threadIdx.x;
    int v=(i<n)?cnt[i]:0;
    int lane=threadIdx.x&31,w=threadIdx.x>>5;
    int incl=v;
    #pragma unroll
    for(int o=1;o<32;o<<=1){int t=__shfl_up_sync(0xffffffffu,incl,o);if(lane>=o)incl+=t;}
    if(lane==31) wsum[w]=incl;
    __syncthreads();
    if(w==0){
        int s=wsum[lane];
        #pragma unroll
        for(int o=1;o<32;o<<=1){int t=__shfl_up_sync(0xffffffffu,s,o);if(lane>=o)s+=t;}
        __syncwarp();
        wsum[lane]=s;
    }
    __syncthreads();
    int prev=(w==0)?0:wsum[w-1];
    if(i<n) base[i]=incl-v+prev+bsums[blockIdx.x];
}

__global__ void place_kernel(const int* __restrict__ rows,const int* __restrict__ cols,
    const float* __restrict__ g1,const float* __restrict__ g2,
    const float* __restrict__ d1,const float* __restrict__ d2,
    const int* __restrict__ base,int* __restrict__ cur,float4* __restrict__ edges,int E)
{
    int e=blockIdx.x*blockDim.x+threadIdx.x;
    if(e>=E) return;
    int r=__ldg(rows+e),c=__ldg(cols+e);
    int slot=__ldg(base+c)+atomicAdd(cur+c,1);
    float4 rec;
    rec.x=__int_as_float(r);
    rec.y=__ldg(g1+e)*__ldg(d1+r)*__ldg(d1+c);
    rec.z=__ldg(g2+e)*__ldg(d2+r)*__ldg(d2+c);
    rec.w=0.0f;
    edges[slot]=rec;
}

__global__ void __launch_bounds__(256)
gather_kernel(const float* __restrict__ h,const float* __restrict__ dinv,
              const int* __restrict__ base,const int* __restrict__ cnt,
              const float4* __restrict__ edges,float* __restrict__ out,int n,int sel)
{
    int node=blockIdx.x*(blockDim.x>>5)+(threadIdx.x>>5);
    if(node>=n) return;
    int lane=threadIdx.x&31;
    float di=__ldg(dinv+node);
    float w0=di*di;
    float4 acc=__ldg((const float4*)(h+(size_t)node*128)+lane);
    acc.x*=w0;acc.y*=w0;acc.z*=w0;acc.w*=w0;
    int s=__ldg(base+node);
    int end=s+__ldg(cnt+node);
    for(;s+4<=end;s+=4){
        float4 e0=__ldg(edges+s),e1=__ldg(edges+s+1),e2=__ldg(edges+s+2),e3=__ldg(edges+s+3);
        int r0=__float_as_int(e0.x),r1=__float_as_int(e1.x),r2=__float_as_int(e2.x),r3=__float_as_int(e3.x);
        float w0_=sel?e0.z:e0.y,w1_=sel?e1.z:e1.y,w2_=sel?e2.z:e2.y,w3_=sel?e3.z:e3.y;
        float4 v0=__ldg((const float4*)(h+(size_t)r0*128)+lane);
        float4 v1=__ldg((const float4*)(h+(size_t)r1*128)+lane);
        float4 v2=__ldg((const float4*)(h+(size_t)r2*128)+lane);
        float4 v3=__ldg((const float4*)(h+(size_t)r3*128)+lane);
        acc.x=fmaf(w0_,v0.x,acc.x);acc.y=fmaf(w0_,v0.y,acc.y);acc.z=fmaf(w0_,v0.z,acc.z);acc.w=fmaf(w0_,v0.w,acc.w);
        acc.x=fmaf(w1_,v1.x,acc.x);acc.y=fmaf(w1_,v1.y,acc.y);acc.z=fmaf(w1_,v1.z,acc.z);acc.w=fmaf(w1_,v1.w,acc.w);
        acc.x=fmaf(w2_,v2.x,acc.x);acc.y=fmaf(w2_,v2.y,acc.y);acc.z=fmaf(w2_,v2.z,acc.z);acc.w=fmaf(w2_,v2.w,acc.w);
        acc.x=fmaf(w3_,v3.x,acc.x);acc.y=fmaf(w3_,v3.y,acc.y);acc.z=fmaf(w3_,v3.z,acc.z);acc.w=fmaf(w3_,v3.w,acc.w);
    }
    for(;s<end;s++){
        float4 e0=__ldg(edges+s);
        int r0=__float_as_int(e0.x);
        float wa=sel?e0.z:e0.y;
        float4 v0=__ldg((const float4*)(h+(size_t)r0*128)+lane);
        acc.x=fmaf(wa,v0.x,acc.x);acc.y=fmaf(wa,v0.y,acc.y);acc.z=fmaf(wa,v0.z,acc.z);acc.w=fmaf(wa,v0.w,acc.w);
    }
    ((float4*)(out+(size_t)node*128))[lane]=acc;
}

extern "C" void kernel_launch(void* const* d_in,const int* in_sizes,int n_in,
                              void* d_out,int out_size)
{
    const float* x=(const float*)d_in[0];
    const int*   ei=(const int*)d_in[1];
    const float* ea=(const float*)d_in[2];
    const float* W1=(const float*)d_in[3];
    const float* m1w1=(const float*)d_in[4];
    const float* m1b1=(const float*)d_in[5];
    const float* m1w2=(const float*)d_in[6];
    const float* m1b2=(const float*)d_in[7];
    const float* W2=(const float*)d_in[8];
    const float* m2w1=(const float*)d_in[9];
    const float* m2b1=(const float*)d_in[10];
    const float* m2w2=(const float*)d_in[11];
    const float* m2b2=(const float*)d_in[12];
    float* out=(float*)d_out;

    int n=in_sizes[0]/128;
    int E=in_sizes[1]/2;
    const int* rows=ei;
    const int* cols=ei+E;
    int nblk=(n+1023)/1024;

    float *ph,*pagg,*pg1,*pg2,*pd1,*pd2;
    float4* pedges;
    int *pcnt,*pcur,*pbase,*pbsums;
    cudaGetSymbolAddress((void**)&ph,g_h);
    cudaGetSymbolAddress((void**)&pagg,g_agg);
    cudaGetSymbolAddress((void**)&pg1,g_g1);
    cudaGetSymbolAddress((void**)&pg2,g_g2);
    cudaGetSymbolAddress((void**)&pd1,g_d1);
    cudaGetSymbolAddress((void**)&pd2,g_d2);
    cudaGetSymbolAddress((void**)&pcnt,g_cnt);
    cudaGetSymbolAddress((void**)&pcur,g_cur);
    cudaGetSymbolAddress((void**)&pbase,g_base);
    cudaGetSymbolAddress((void**)&pbsums,g_bsums);
    cudaGetSymbolAddress((void**)&pedges,g_edges);

    const int GATE_SMEM=(2*48*136+512)*4;        // 54272 B
    const int GEMM_SMEM=(128*136+8*16*132)*4;    // 137216 B
    cudaFuncSetAttribute(gate_mma_kernel,cudaFuncAttributeMaxDynamicSharedMemorySize,GATE_SMEM);
    cudaFuncSetAttribute(gemm_mma_kernel,cudaFuncAttributeMaxDynamicSharedMemorySize,GEMM_SMEM);

    // Fork a side stream inside capture (event fork-join; host objects leak —
    // kernel_launch only runs a handful of times, replays don't re-run host code).
    cudaStream_t s2;
    cudaStreamCreateWithFlags(&s2,cudaStreamNonBlocking);
    cudaEvent_t evF,evB;
    cudaEventCreateWithFlags(&evF,cudaEventDisableTiming);
    cudaEventCreateWithFlags(&evB,cudaEventDisableTiming);

    cudaEventRecord(evF,0);
    cudaStreamWaitEvent(s2,evF,0);

    // s2: count histogram + scans + gemm1 (independent of the gate)
    zero_cnt_kernel<<<(n+255)/256,256,0,s2>>>(pcnt,n);
    hist_kernel<<<(E+255)/256,256,0,s2>>>(cols,pcnt,E);
    scan_block_sums<<<nblk,1024,0,s2>>>(pcnt,pbsums,n);
    scan_bsums_excl<<<1,32,0,s2>>>(pbsums,nblk);
    scan_final<<<nblk,1024,0,s2>>>(pcnt,pbsums,pbase,n);
    gemm_mma_kernel<<<148,256,GEMM_SMEM,s2>>>(x,W1,ph,n,0);
    cudaEventRecord(evB,s2);

    // stream 0: gate + degree path
    init_kernel<<<(n+255)/256,256>>>(pd1,pd2,pcur,n);
    gate_mma_kernel<<<296,256,GATE_SMEM>>>(ea,m1w1,m1b1,m1w2,m1b2,m2w1,m2b1,m2w2,m2b2,
                                           cols,pg1,pg2,pd1,pd2,E);
    rsqrt_kernel<<<(n+255)/256,256>>>(pd1,pd2,n);

    cudaStreamWaitEvent(0,evB,0);   // join: need base (scans) + g_h (gemm1)

    place_kernel<<<(E+255)/256,256>>>(rows,cols,pg1,pg2,pd1,pd2,pbase,pcur,pedges,E);
    gather_kernel<<<(n+7)/8,256>>>(ph,pd1,pbase,pcnt,pedges,pagg,n,0);
    gemm_mma_kernel<<<148,256,GEMM_SMEM>>>(pagg,W2,ph,n,1);
    gather_kernel<<<(n+7)/8,256>>>(ph,pd2,pbase,pcnt,pedges,out,n,1);
}

// round 10
// speedup vs baseline: 1.4675x; 1.4675x over previous
#include <cuda_runtime.h>
#include <math.h>
#include <cstdint>

#define MAXN 100000
#define MAXE 1600000
#define NBLK 98
typedef unsigned long long u64;

__device__ __forceinline__ float tf32_hi(float x){return __uint_as_float(__float_as_uint(x)&0xffffe000u);}

// m16n8k8 tf32 mma (sm_80+ PTX)
__device__ __forceinline__ void mma8(float* c,const uint32_t* a,uint32_t b0,uint32_t b1){
    asm volatile("mma.sync.aligned.m16n8k8.row.col.f32.tf32.tf32.f32 "
                 "{%0,%1,%2,%3},{%4,%5,%6,%7},{%8,%9},{%0,%1,%2,%3};"
        :"+f"(c[0]),"+f"(c[1]),"+f"(c[2]),"+f"(c[3])
        :"r"(a[0]),"r"(a[1]),"r"(a[2]),"r"(a[3]),"r"(b0),"r"(b1));
}

__device__ float  g_h[(size_t)MAXN*128];    // h' = dinv[r] * (X@W)[r]
__device__ float  g_agg[(size_t)MAXN*128];
__device__ float  g_d1[MAXN];
__device__ float  g_d2[MAXN];
__device__ int    g_cnt[MAXN];
__device__ int    g_cur[MAXN];
__device__ int    g_base[MAXN];
__device__ int    g_bsums[NBLK+1];
__device__ float2 g_e1[MAXE];               // CSR slot: {row(bits), g1}
__device__ float2 g_e2[MAXE];               // CSR slot: {row(bits), g2}

__global__ void init_kernel(float*d1,float*d2,int*cnt,int*cur,int n){
    int i=blockIdx.x*blockDim.x+threadIdx.x;
    if(i<n){d1[i]=1.0f;d2[i]=1.0f;cnt[i]=0;cur[i]=0;}
}
__global__ void hist_kernel(const int* __restrict__ cols,int* __restrict__ cnt,int E){
    int e=blockIdx.x*blockDim.x+threadIdx.x;
    if(e<E) atomicAdd(cnt+__ldg(cols+e),1);
}

// ---------------------------------------------------------------------------
// Tensor-core gate (split-fp32 tf32, K=48, bias in C-init). Writes CSR edge
// records directly (base/cur ready before launch): e1[slot]={row,g1},
// e2[slot]={row,g2}; accumulates weighted degrees.
__global__ void __launch_bounds__(256) gate_mma_kernel(
    const float* __restrict__ ea,
    const float* __restrict__ m1w1,const float* __restrict__ m1b1,
    const float* __restrict__ m1w2,const float* __restrict__ m1b2,
    const float* __restrict__ m2w1,const float* __restrict__ m2b1,
    const float* __restrict__ m2w2,const float* __restrict__ m2b2,
    const int* __restrict__ rows,const int* __restrict__ cols,
    const int* __restrict__ base,int* __restrict__ cur,
    float2* __restrict__ e1,float2* __restrict__ e2,
    float* __restrict__ deg1,float* __restrict__ deg2,int E)
{
    extern __shared__ float ds[];
    float* biasp=ds+2*48*136;
    float* w2p  =biasp+256;
    int tid=threadIdx.x;

    for(int idx=tid;idx<2*48*128;idx+=256){
        int layer=idx/6144,rem=idx%6144,k=rem>>7,n=rem&127;
        const float* W=layer?m2w1:m1w1;
        float v;
        if(k<16)      v=tf32_hi(__ldg(W+k*128+n));
        else if(k<32) v=tf32_hi(__ldg(W+(k-16)*128+n));
        else          {float w=__ldg(W+(k-32)*128+n);v=w-tf32_hi(w);}
        ds[layer*6528+k*136+n]=v;
    }
    if(tid<256){
        biasp[tid]=(tid<128)?__ldg(m1b1+tid):__ldg(m2b1+tid-128);
        w2p[tid]  =(tid<128)?__ldg(m1w2+tid):__ldg(m2w2+tid-128);
    }
    __syncthreads();

    int lane=tid&31,g=lane>>2,t=lane&3;
    int w=blockIdx.x*(blockDim.x>>5)+(tid>>5);
    int nwarps=gridDim.x*(blockDim.x>>5);
    int ntask=(E+63)>>6;
    float b2v[2]={__ldg(m1b2),__ldg(m2b2)};

    for(int task=w;task<ntask;task+=nwarps){
        int e0=task*64;
        uint32_t Ahi[4][8],Alo[4][8];
        #pragma unroll
        for(int mt=0;mt<4;mt++){
            int r1=e0+mt*16+g,r2=r1+8;
            #pragma unroll
            for(int j=0;j<4;j++){
                int ac=(j&1)*4+(j>>1)*8+t;
                int fi=(j>>1)*4+(j&1)*2;
                float v1=(r1<E)?__ldg(ea+(size_t)r1*16+ac):0.f;
                float v2=(r2<E)?__ldg(ea+(size_t)r2*16+ac):0.f;
                uint32_t h1=__float_as_uint(v1)&0xffffe000u;
                uint32_t h2=__float_as_uint(v2)&0xffffe000u;
                Ahi[mt][fi]=h1;  Ahi[mt][fi+1]=h2;
                Alo[mt][fi]=__float_as_uint(v1-__uint_as_float(h1));
                Alo[mt][fi+1]=__float_as_uint(v2-__uint_as_float(h2));
            }
        }
        int slotA[4]={-1,-1,-1,-1},slotB[4]={-1,-1,-1,-1};
        #pragma unroll
        for(int layer=0;layer<2;layer++){
            const float* Bl=ds+layer*6528;
            const float* biasl=biasp+layer*128;
            const float* w2l=w2p+layer*128;
            float p0[4]={0,0,0,0},p1[4]={0,0,0,0};
            #pragma unroll 1
            for(int nt=0;nt<16;nt++){
                int n0=nt*8;
                float bA=biasl[n0+2*t],bB=biasl[n0+2*t+1];
                float c[4][4];
                #pragma unroll
                for(int mt=0;mt<4;mt++){c[mt][0]=bA;c[mt][1]=bB;c[mt][2]=bA;c[mt][3]=bB;}
                #define STEP(AARR,OFF,K0) do{                                   \
                    uint32_t b0=__float_as_uint(Bl[(K0+t)*136+n0+g]);           \
                    uint32_t b1v=__float_as_uint(Bl[(K0+t+4)*136+n0+g]);        \
                    _Pragma("unroll")                                           \
                    for(int mt=0;mt<4;mt++) mma8(c[mt],&AARR[mt][OFF],b0,b1v);  \
                }while(0)
                STEP(Ahi,0,0);  STEP(Ahi,4,8);
                STEP(Alo,0,16); STEP(Alo,4,24);
                STEP(Ahi,0,32); STEP(Ahi,4,40);
                #undef STEP
                float wA=w2l[n0+2*t],wB=w2l[n0+2*t+1];
                #pragma unroll
                for(int mt=0;mt<4;mt++){
                    p0[mt]+=fmaxf(c[mt][0],0.f)*wA+fmaxf(c[mt][1],0.f)*wB;
                    p1[mt]+=fmaxf(c[mt][2],0.f)*wA+fmaxf(c[mt][3],0.f)*wB;
                }
            }
            #pragma unroll
            for(int mt=0;mt<4;mt++){
                p0[mt]+=__shfl_xor_sync(0xffffffffu,p0[mt],1);
                p0[mt]+=__shfl_xor_sync(0xffffffffu,p0[mt],2);
                p1[mt]+=__shfl_xor_sync(0xffffffffu,p1[mt],1);
                p1[mt]+=__shfl_xor_sync(0xffffffffu,p1[mt],2);
            }
            if(t==0){
                float b2=b2v[layer];
                #pragma unroll
                for(int mt=0;mt<4;mt++){
                    int e=e0+mt*16+g,e2i=e+8;
                    if(layer==0){
                        if(e<E){
                            float gg=1.0f/(1.0f+expf(-(p0[mt]+b2)));
                            int c_=__ldg(cols+e),r_=__ldg(rows+e);
                            int slot=__ldg(base+c_)+atomicAdd(cur+c_,1);
                            slotA[mt]=slot;
                            e1[slot]=make_float2(__int_as_float(r_),gg);
                            atomicAdd(deg1+c_,gg);
                        }
                        if(e2i<E){
                            float gg=1.0f/(1.0f+expf(-(p1[mt]+b2)));
                            int c_=__ldg(cols+e2i),r_=__ldg(rows+e2i);
                            int slot=__ldg(base+c_)+atomicAdd(cur+c_,1);
                            slotB[mt]=slot;
                            e1[slot]=make_float2(__int_as_float(r_),gg);
                            atomicAdd(deg1+c_,gg);
                        }
                    }else{
                        if(slotA[mt]>=0){
                            float gg=1.0f/(1.0f+expf(-(p0[mt]+b2)));
                            int c_=__ldg(cols+e),r_=__ldg(rows+e);
                            e2[slotA[mt]]=make_float2(__int_as_float(r_),gg);
                            atomicAdd(deg2+c_,gg);
                        }
                        if(slotB[mt]>=0){
                            float gg=1.0f/(1.0f+expf(-(p1[mt]+b2)));
                            int c_=__ldg(cols+e2i),r_=__ldg(rows+e2i);
                            e2[slotB[mt]]=make_float2(__int_as_float(r_),gg);
                            atomicAdd(deg2+c_,gg);
                        }
                    }
                }
            }
        }
    }
}

// ---------------------------------------------------------------------------
// Dense GEMM via mma.sync tf32 split-fp32; epilogue scales row r by dinv[r].
__global__ void __launch_bounds__(256) gemm_mma_kernel(
    const float* __restrict__ X,const float* __restrict__ W,
    const float* __restrict__ dinv,
    float* __restrict__ out,int n,int relu_in)
{
    extern __shared__ float sm[];
    float* Ws=sm;                 // 128*136
    float* Xs=sm+128*136;         // 8 warps * 16*132
    int tid=threadIdx.x,wid=tid>>5,lane=tid&31;
    int g=lane>>2,t=lane&3;

    for(int idx=tid;idx<128*32;idx+=256){
        int k=idx>>5,nn=(idx&31)*4;
        float4 v=__ldg((const float4*)(W+k*128+nn));
        float* d=Ws+k*136+nn;
        d[0]=v.x;d[1]=v.y;d[2]=v.z;d[3]=v.w;
    }
    __syncthreads();

    float* Xw=Xs+wid*(16*132);
    int ntiles=(n+127)>>7;
    for(int tile=blockIdx.x;tile<ntiles;tile+=gridDim.x){
        int r0=tile*128+wid*16;
        #pragma unroll 4
        for(int i=0;i<16;i++){
            int r=r0+i;
            float4 v=make_float4(0.f,0.f,0.f,0.f);
            if(r<n) v=__ldg((const float4*)(X+(size_t)r*128)+lane);
            if(relu_in){v.x=fmaxf(v.x,0.f);v.y=fmaxf(v.y,0.f);v.z=fmaxf(v.z,0.f);v.w=fmaxf(v.w,0.f);}
            float* d=Xw+i*132+lane*4;
            d[0]=v.x;d[1]=v.y;d[2]=v.z;d[3]=v.w;
        }
        __syncwarp();

        float c[16][4];
        #pragma unroll
        for(int nf=0;nf<16;nf++){c[nf][0]=0.f;c[nf][1]=0.f;c[nf][2]=0.f;c[nf][3]=0.f;}

        #pragma unroll 1
        for(int ks=0;ks<16;ks++){
            int k0=ks*8;
            float x0=Xw[g*132+k0+t],x1=Xw[(g+8)*132+k0+t];
            float x2=Xw[g*132+k0+t+4],x3=Xw[(g+8)*132+k0+t+4];
            uint32_t ahi[4],alo[4];
            ahi[0]=__float_as_uint(x0)&0xffffe000u; alo[0]=__float_as_uint(x0-__uint_as_float(ahi[0]));
            ahi[1]=__float_as_uint(x1)&0xffffe000u; alo[1]=__float_as_uint(x1-__uint_as_float(ahi[1]));
            ahi[2]=__float_as_uint(x2)&0xffffe000u; alo[2]=__float_as_uint(x2-__uint_as_float(ahi[2]));
            ahi[3]=__float_as_uint(x3)&0xffffe000u; alo[3]=__float_as_uint(x3-__uint_as_float(ahi[3]));
            #pragma unroll
            for(int nf=0;nf<16;nf++){
                int n0=nf*8;
                float b0r=Ws[(k0+t)*136+n0+g],b1r=Ws[(k0+t+4)*136+n0+g];
                uint32_t bh0=__float_as_uint(b0r)&0xffffe000u;
                uint32_t bh1=__float_as_uint(b1r)&0xffffe000u;
                uint32_t bl0=__float_as_uint(b0r-__uint_as_float(bh0));
                uint32_t bl1=__float_as_uint(b1r-__uint_as_float(bh1));
                mma8(c[nf],ahi,bh0,bh1);
                mma8(c[nf],alo,bh0,bh1);
                mma8(c[nf],ahi,bl0,bl1);
            }
        }

        int ra=r0+g,rb=r0+g+8;
        float da=(ra<n)?__ldg(dinv+ra):0.f;
        float db=(rb<n)?__ldg(dinv+rb):0.f;
        #pragma unroll
        for(int nf=0;nf<16;nf++){
            int col=nf*8+2*t;
            if(ra<n) *(float2*)(out+(size_t)ra*128+col)=make_float2(c[nf][0]*da,c[nf][1]*da);
            if(rb<n) *(float2*)(out+(size_t)rb*128+col)=make_float2(c[nf][2]*db,c[nf][3]*db);
        }
        __syncwarp();
    }
}

__global__ void rsqrt_kernel(float*d1,float*d2,int n){
    int i=blockIdx.x*blockDim.x+threadIdx.x;
    if(i<n){d1[i]=rsqrtf(d1[i]);d2[i]=rsqrtf(d2[i]);}
}

__global__ void scan_block_sums(const int* __restrict__ cnt,int* __restrict__ bsums,int n){
    __shared__ int wsum[32];
    int i=blockIdx.x*1024+threadIdx.x;
    int v=(i<n)?cnt[i]:0;
    #pragma unroll
    for(int o=16;o;o>>=1) v+=__shfl_down_sync(0xffffffffu,v,o);
    if((threadIdx.x&31)==0) wsum[threadIdx.x>>5]=v;
    __syncthreads();
    if(threadIdx.x<32){
        int s=wsum[threadIdx.x];
        #pragma unroll
        for(int o=16;o;o>>=1) s+=__shfl_down_sync(0xffffffffu,s,o);
        if(threadIdx.x==0) bsums[blockIdx.x]=s;
    }
}
__global__ void scan_bsums_excl(int*bsums,int nb){
    if(threadIdx.x==0&&blockIdx.x==0){
        int acc=0;
        for(int i=0;i<nb;i++){int t=bsums[i];bsums[i]=acc;acc+=t;}
    }
}
__global__ void scan_final(const int* __restrict__ cnt,const int* __restrict__ bsums,
                           int* __restrict__ base,int n){
    __shared__ int wsum[32];
    int i=blockIdx.x*1024+threadIdx.x;
    int v=(i<n)?cnt[i]:0;
    int lane=threadIdx.x&31,w=threadIdx.x>>5;
    int incl=v;
    #pragma unroll
    for(int o=1;o<32;o<<=1){int t=__shfl_up_sync(0xffffffffu,incl,o);if(lane>=o)incl+=t;}
    if(lane==31) wsum[w]=incl;
    __syncthreads();
    if(w==0){
        int s=wsum[lane];
        #pragma unroll
        for(int o=1;o<32;o<<=1){int t=__shfl_up_sync(0xffffffffu,s,o);if(lane>=o)s+=t;}
        __syncwarp();
        wsum[lane]=s;
    }
    __syncthreads();
    int prev=(w==0)?0:wsum[w-1];
    if(i<n) base[i]=incl-v+prev+bsums[blockIdx.x];
}

// ---------------------------------------------------------------------------
// Gather: out[i] = dinv[i] * ( h'[i] + sum_{s in CSR(i)} g[s]*h'[row[s]] )
__global__ void __launch_bounds__(256)
gather_kernel(const float* __restrict__ h,const float* __restrict__ dinv,
              const int* __restrict__ base,const int* __restrict__ cnt,
              const float2* __restrict__ edges,float* __restrict__ out,int n)
{
    int node=blockIdx.x*(blockDim.x>>5)+(threadIdx.x>>5);
    if(node>=n) return;
    int lane=threadIdx.x&31;
    float4 acc=__ldg((const float4*)(h+(size_t)node*128)+lane);
    int s=__ldg(base+node);
    int end=s+__ldg(cnt+node);
    for(;s+4<=end;s+=4){
        float2 e0=__ldg(edges+s),e1=__ldg(edges+s+1),e2=__ldg(edges+s+2),e3=__ldg(edges+s+3);
        int r0=__float_as_int(e0.x),r1=__float_as_int(e1.x),r2=__float_as_int(e2.x),r3=__float_as_int(e3.x);
        float4 v0=__ldg((const float4*)(h+(size_t)r0*128)+lane);
        float4 v1=__ldg((const float4*)(h+(size_t)r1*128)+lane);
        float4 v2=__ldg((const float4*)(h+(size_t)r2*128)+lane);
        float4 v3=__ldg((const float4*)(h+(size_t)r3*128)+lane);
        acc.x=fmaf(e0.y,v0.x,acc.x);acc.y=fmaf(e0.y,v0.y,acc.y);acc.z=fmaf(e0.y,v0.z,acc.z);acc.w=fmaf(e0.y,v0.w,acc.w);
        acc.x=fmaf(e1.y,v1.x,acc.x);acc.y=fmaf(e1.y,v1.y,acc.y);acc.z=fmaf(e1.y,v1.z,acc.z);acc.w=fmaf(e1.y,v1.w,acc.w);
        acc.x=fmaf(e2.y,v2.x,acc.x);acc.y=fmaf(e2.y,v2.y,acc.y);acc.z=fmaf(e2.y,v2.z,acc.z);acc.w=fmaf(e2.y,v2.w,acc.w);
        acc.x=fmaf(e3.y,v3.x,acc.x);acc.y=fmaf(e3.y,v3.y,acc.y);acc.z=fmaf(e3.y,v3.z,acc.z);acc.w=fmaf(e3.y,v3.w,acc.w);
    }
    for(;s<end;s++){
        float2 e0=__ldg(edges+s);
        int r0=__float_as_int(e0.x);
        float4 v0=__ldg((const float4*)(h+(size_t)r0*128)+lane);
        acc.x=fmaf(e0.y,v0.x,acc.x);acc.y=fmaf(e0.y,v0.y,acc.y);acc.z=fmaf(e0.y,v0.z,acc.z);acc.w=fmaf(e0.y,v0.w,acc.w);
    }
    float di=__ldg(dinv+node);
    acc.x*=di;acc.y*=di;acc.z*=di;acc.w*=di;
    ((float4*)(out+(size_t)node*128))[lane]=acc;
}

extern "C" void kernel_launch(void* const* d_in,const int* in_sizes,int n_in,
                              void* d_out,int out_size)
{
    const float* x=(const float*)d_in[0];
    const int*   ei=(const int*)d_in[1];
    const float* ea=(const float*)d_in[2];
    const float* W1=(const float*)d_in[3];
    const float* m1w1=(const float*)d_in[4];
    const float* m1b1=(const float*)d_in[5];
    const float* m1w2=(const float*)d_in[6];
    const float* m1b2=(const float*)d_in[7];
    const float* W2=(const float*)d_in[8];
    const float* m2w1=(const float*)d_in[9];
    const float* m2b1=(const float*)d_in[10];
    const float* m2w2=(const float*)d_in[11];
    const float* m2b2=(const float*)d_in[12];
    float* out=(float*)d_out;

    int n=in_sizes[0]/128;
    int E=in_sizes[1]/2;
    const int* rows=ei;
    const int* cols=ei+E;
    int nblk=(n+1023)/1024;

    float *ph,*pagg,*pd1,*pd2;
    float2 *pe1,*pe2;
    int *pcnt,*pcur,*pbase,*pbsums;
    cudaGetSymbolAddress((void**)&ph,g_h);
    cudaGetSymbolAddress((void**)&pagg,g_agg);
    cudaGetSymbolAddress((void**)&pd1,g_d1);
    cudaGetSymbolAddress((void**)&pd2,g_d2);
    cudaGetSymbolAddress((void**)&pcnt,g_cnt);
    cudaGetSymbolAddress((void**)&pcur,g_cur);
    cudaGetSymbolAddress((void**)&pbase,g_base);
    cudaGetSymbolAddress((void**)&pbsums,g_bsums);
    cudaGetSymbolAddress((void**)&pe1,g_e1);
    cudaGetSymbolAddress((void**)&pe2,g_e2);

    const int GATE_SMEM=(2*48*136+512)*4;        // 54272 B
    const int GEMM_SMEM=(128*136+8*16*132)*4;    // 137216 B
    cudaFuncSetAttribute(gate_mma_kernel,cudaFuncAttributeMaxDynamicSharedMemorySize,GATE_SMEM);
    cudaFuncSetAttribute(gemm_mma_kernel,cudaFuncAttributeMaxDynamicSharedMemorySize,GEMM_SMEM);

    // CSR layout first (depends only on cols), then gate writes slots directly.
    init_kernel<<<(n+255)/256,256>>>(pd1,pd2,pcnt,pcur,n);
    hist_kernel<<<(E+255)/256,256>>>(cols,pcnt,E);
    scan_block_sums<<<nblk,1024>>>(pcnt,pbsums,n);
    scan_bsums_excl<<<1,32>>>(pbsums,nblk);
    scan_final<<<nblk,1024>>>(pcnt,pbsums,pbase,n);

    gate_mma_kernel<<<296,256,GATE_SMEM>>>(ea,m1w1,m1b1,m1w2,m1b2,m2w1,m2b1,m2w2,m2b2,
                                           rows,cols,pbase,pcur,pe1,pe2,pd1,pd2,E);
    rsqrt_kernel<<<(n+255)/256,256>>>(pd1,pd2,n);

    gemm_mma_kernel<<<148,256,GEMM_SMEM>>>(x,W1,pd1,ph,n,0);
    gather_kernel<<<(n+7)/8,256>>>(ph,pd1,pbase,pcnt,pe1,pagg,n);

    gemm_mma_kernel<<<148,256,GEMM_SMEM>>>(pagg,W2,pd2,ph,n,1);
    gather_kernel<<<(n+7)/8,256>>>(ph,pd2,pbase,pcnt,pe2,out,n);
}

// round 11
// speedup vs baseline: 1.7652x; 1.2029x over previous
#include <cuda_runtime.h>
#include <cuda_bf16.h>
#include <math.h>
#include <cstdint>

#define MAXN 100000
#define MAXE 1600000
#define NBLK 98

// bf16 m16n8k16 mma (sm_80+ PTX)
__device__ __forceinline__ void mma16(float* c,const uint32_t* a,uint32_t b0,uint32_t b1){
    asm volatile("mma.sync.aligned.m16n8k16.row.col.f32.bf16.bf16.f32 "
                 "{%0,%1,%2,%3},{%4,%5,%6,%7},{%8,%9},{%0,%1,%2,%3};"
        :"+f"(c[0]),"+f"(c[1]),"+f"(c[2]),"+f"(c[3])
        :"r"(a[0]),"r"(a[1]),"r"(a[2]),"r"(a[3]),"r"(b0),"r"(b1));
}
// split (x0,x1) into packed bf16 hi pair + bf16 residual pair
__device__ __forceinline__ void split2(float x0,float x1,uint32_t&hi,uint32_t&lo){
    __nv_bfloat16 h0=__float2bfloat16(x0),h1=__float2bfloat16(x1);
    float f0=__bfloat162float(h0),f1=__bfloat162float(h1);
    __nv_bfloat16 l0=__float2bfloat16(x0-f0),l1=__float2bfloat16(x1-f1);
    hi=(uint32_t)reinterpret_cast<unsigned short&>(h0)|((uint32_t)reinterpret_cast<unsigned short&>(h1)<<16);
    lo=(uint32_t)reinterpret_cast<unsigned short&>(l0)|((uint32_t)reinterpret_cast<unsigned short&>(l1)<<16);
}

__device__ float  g_h[(size_t)MAXN*128];    // h' = dinv[r]*(X@W)[r]
__device__ float  g_agg[(size_t)MAXN*128];
__device__ float  g_d1[MAXN];
__device__ float  g_d2[MAXN];
__device__ int    g_cnt[MAXN];
__device__ int    g_cur[MAXN];
__device__ int    g_base[MAXN];
__device__ int    g_bsums[NBLK+1];
__device__ float2 g_e1[MAXE];               // CSR slot: {row(bits), g1}
__device__ float2 g_e2[MAXE];               // CSR slot: {row(bits), g2}

__global__ void init_kernel(float*d1,float*d2,int*cnt,int*cur,int n){
    int i=blockIdx.x*blockDim.x+threadIdx.x;
    if(i<n){d1[i]=1.0f;d2[i]=1.0f;cnt[i]=0;cur[i]=0;}
}
__global__ void hist_kernel(const int* __restrict__ cols,int* __restrict__ cnt,int E){
    int e=blockIdx.x*blockDim.x+threadIdx.x;
    if(e<E) atomicAdd(cnt+__ldg(cols+e),1);
}

// ---------------------------------------------------------------------------
// Gate: bf16 3-term split MMA (K=16 in one chunk). Writes CSR records directly.
// smem (u32): B[2 layer][2 term][8 k2][136] = 4352 | bias(f32) 256 | w2(f32) 256
__global__ void __launch_bounds__(256) gate_mma_kernel(
    const float* __restrict__ ea,
    const float* __restrict__ m1w1,const float* __restrict__ m1b1,
    const float* __restrict__ m1w2,const float* __restrict__ m1b2,
    const float* __restrict__ m2w1,const float* __restrict__ m2b1,
    const float* __restrict__ m2w2,const float* __restrict__ m2b2,
    const int* __restrict__ rows,const int* __restrict__ cols,
    const int* __restrict__ base,int* __restrict__ cur,
    float2* __restrict__ e1,float2* __restrict__ e2,
    float* __restrict__ deg1,float* __restrict__ deg2,int E)
{
    extern __shared__ float ds[];
    uint32_t* dsu=(uint32_t*)ds;
    float* biasp=ds+4352;
    float* w2p  =ds+4608;
    int tid=threadIdx.x;

    for(int idx=tid;idx<2048;idx+=256){
        int layer=idx>>10,rem=idx&1023,k2=rem>>7,n=rem&127;
        const float* W=layer?m2w1:m1w1;
        float w0=__ldg(W+(2*k2)*128+n),w1=__ldg(W+(2*k2+1)*128+n);
        uint32_t hi,lo; split2(w0,w1,hi,lo);
        dsu[layer*2176+k2*136+n]=hi;
        dsu[layer*2176+1088+k2*136+n]=lo;
    }
    if(tid<256){
        biasp[tid]=(tid<128)?__ldg(m1b1+tid):__ldg(m2b1+tid-128);
        w2p[tid]  =(tid<128)?__ldg(m1w2+tid):__ldg(m2w2+tid-128);
    }
    __syncthreads();

    int lane=tid&31,g=lane>>2,t=lane&3;
    int w=blockIdx.x*(blockDim.x>>5)+(tid>>5);
    int nwarps=gridDim.x*(blockDim.x>>5);
    int ntask=(E+63)>>6;
    float b2v[2]={__ldg(m1b2),__ldg(m2b2)};

    for(int task=w;task<ntask;task+=nwarps){
        int e0=task*64;
        uint32_t Ahi[4][4],Alo[4][4];
        #pragma unroll
        for(int mt=0;mt<4;mt++){
            int r1=e0+mt*16+g,r2=r1+8;
            float2 z=make_float2(0.f,0.f);
            float2 v1a=(r1<E)?*(const float2*)(ea+(size_t)r1*16+2*t):z;
            float2 v1b=(r1<E)?*(const float2*)(ea+(size_t)r1*16+8+2*t):z;
            float2 v2a=(r2<E)?*(const float2*)(ea+(size_t)r2*16+2*t):z;
            float2 v2b=(r2<E)?*(const float2*)(ea+(size_t)r2*16+8+2*t):z;
            split2(v1a.x,v1a.y,Ahi[mt][0],Alo[mt][0]);
            split2(v2a.x,v2a.y,Ahi[mt][1],Alo[mt][1]);
            split2(v1b.x,v1b.y,Ahi[mt][2],Alo[mt][2]);
            split2(v2b.x,v2b.y,Ahi[mt][3],Alo[mt][3]);
        }
        int slotA[4]={-1,-1,-1,-1},slotB[4]={-1,-1,-1,-1};
        #pragma unroll
        for(int layer=0;layer<2;layer++){
            const uint32_t* Bh=dsu+layer*2176;
            const uint32_t* Bl=Bh+1088;
            const float* biasl=biasp+layer*128;
            const float* w2l=w2p+layer*128;
            float p0[4]={0,0,0,0},p1[4]={0,0,0,0};
            #pragma unroll 1
            for(int nt=0;nt<16;nt++){
                int n0=nt*8;
                float bA=biasl[n0+2*t],bB=biasl[n0+2*t+1];
                float c[4][4];
                #pragma unroll
                for(int mt=0;mt<4;mt++){c[mt][0]=bA;c[mt][1]=bB;c[mt][2]=bA;c[mt][3]=bB;}
                uint32_t b0h=Bh[t*136+n0+g],b1h=Bh[(t+4)*136+n0+g];
                uint32_t b0l=Bl[t*136+n0+g],b1l=Bl[(t+4)*136+n0+g];
                #pragma unroll
                for(int mt=0;mt<4;mt++){
                    mma16(c[mt],Ahi[mt],b0h,b1h);
                    mma16(c[mt],Alo[mt],b0h,b1h);
                    mma16(c[mt],Ahi[mt],b0l,b1l);
                }
                float wA=w2l[n0+2*t],wB=w2l[n0+2*t+1];
                #pragma unroll
                for(int mt=0;mt<4;mt++){
                    p0[mt]+=fmaxf(c[mt][0],0.f)*wA+fmaxf(c[mt][1],0.f)*wB;
                    p1[mt]+=fmaxf(c[mt][2],0.f)*wA+fmaxf(c[mt][3],0.f)*wB;
                }
            }
            #pragma unroll
            for(int mt=0;mt<4;mt++){
                p0[mt]+=__shfl_xor_sync(0xffffffffu,p0[mt],1);
                p0[mt]+=__shfl_xor_sync(0xffffffffu,p0[mt],2);
                p1[mt]+=__shfl_xor_sync(0xffffffffu,p1[mt],1);
                p1[mt]+=__shfl_xor_sync(0xffffffffu,p1[mt],2);
            }
            if(t==0){
                float b2=b2v[layer];
                #pragma unroll
                for(int mt=0;mt<4;mt++){
                    int e=e0+mt*16+g,e2i=e+8;
                    if(layer==0){
                        if(e<E){
                            float gg=1.0f/(1.0f+expf(-(p0[mt]+b2)));
                            int c_=__ldg(cols+e),r_=__ldg(rows+e);
                            int slot=__ldg(base+c_)+atomicAdd(cur+c_,1);
                            slotA[mt]=slot;
                            e1[slot]=make_float2(__int_as_float(r_),gg);
                            atomicAdd(deg1+c_,gg);
                        }
                        if(e2i<E){
                            float gg=1.0f/(1.0f+expf(-(p1[mt]+b2)));
                            int c_=__ldg(cols+e2i),r_=__ldg(rows+e2i);
                            int slot=__ldg(base+c_)+atomicAdd(cur+c_,1);
                            slotB[mt]=slot;
                            e1[slot]=make_float2(__int_as_float(r_),gg);
                            atomicAdd(deg1+c_,gg);
                        }
                    }else{
                        if(slotA[mt]>=0){
                            float gg=1.0f/(1.0f+expf(-(p0[mt]+b2)));
                            int c_=__ldg(cols+e),r_=__ldg(rows+e);
                            e2[slotA[mt]]=make_float2(__int_as_float(r_),gg);
                            atomicAdd(deg2+c_,gg);
                        }
                        if(slotB[mt]>=0){
                            float gg=1.0f/(1.0f+expf(-(p1[mt]+b2)));
                            int c_=__ldg(cols+e2i),r_=__ldg(rows+e2i);
                            e2[slotB[mt]]=make_float2(__int_as_float(r_),gg);
                            atomicAdd(deg2+c_,gg);
                        }
                    }
                }
            }
        }
    }
}

// ---------------------------------------------------------------------------
// Dense GEMM: bf16 3-term split, K=16 chunks; epilogue scales row by dinv[r].
// smem (u32): Wh[64][136] | Wl[64][136] | then Xs fp32 (8 warps * 16*132)
__global__ void __launch_bounds__(256) gemm_mma_kernel(
    const float* __restrict__ X,const float* __restrict__ W,
    const float* __restrict__ dinv,
    float* __restrict__ out,int n,int relu_in)
{
    extern __shared__ float sm[];
    uint32_t* Wh=(uint32_t*)sm;       // 8704
    uint32_t* Wl=Wh+8704;             // 8704
    float* Xs=sm+17408;
    int tid=threadIdx.x,wid=tid>>5,lane=tid&31;
    int g=lane>>2,t=lane&3;

    for(int idx=tid;idx<8192;idx+=256){
        int k2=idx>>7,nn=idx&127;
        float w0=__ldg(W+(2*k2)*128+nn),w1=__ldg(W+(2*k2+1)*128+nn);
        uint32_t hi,lo; split2(w0,w1,hi,lo);
        Wh[k2*136+nn]=hi; Wl[k2*136+nn]=lo;
    }
    __syncthreads();

    float* Xw=Xs+wid*(16*132);
    int ntiles=(n+127)>>7;
    for(int tile=blockIdx.x;tile<ntiles;tile+=gridDim.x){
        int r0=tile*128+wid*16;
        #pragma unroll 4
        for(int i=0;i<16;i++){
            int r=r0+i;
            float4 v=make_float4(0.f,0.f,0.f,0.f);
            if(r<n) v=__ldg((const float4*)(X+(size_t)r*128)+lane);
            if(relu_in){v.x=fmaxf(v.x,0.f);v.y=fmaxf(v.y,0.f);v.z=fmaxf(v.z,0.f);v.w=fmaxf(v.w,0.f);}
            float* d=Xw+i*132+lane*4;
            d[0]=v.x;d[1]=v.y;d[2]=v.z;d[3]=v.w;
        }
        __syncwarp();

        float c[16][4];
        #pragma unroll
        for(int nf=0;nf<16;nf++){c[nf][0]=0.f;c[nf][1]=0.f;c[nf][2]=0.f;c[nf][3]=0.f;}

        #pragma unroll 1
        for(int ks=0;ks<8;ks++){
            int k0=ks*16,kb=ks*8;
            float2 xa=*(const float2*)(Xw+g*132+k0+2*t);
            float2 xb=*(const float2*)(Xw+(g+8)*132+k0+2*t);
            float2 xc=*(const float2*)(Xw+g*132+k0+8+2*t);
            float2 xd=*(const float2*)(Xw+(g+8)*132+k0+8+2*t);
            uint32_t ahi[4],alo[4];
            split2(xa.x,xa.y,ahi[0],alo[0]);
            split2(xb.x,xb.y,ahi[1],alo[1]);
            split2(xc.x,xc.y,ahi[2],alo[2]);
            split2(xd.x,xd.y,ahi[3],alo[3]);
            #pragma unroll
            for(int nf=0;nf<16;nf++){
                int n0=nf*8;
                uint32_t b0h=Wh[(kb+t)*136+n0+g],b1h=Wh[(kb+t+4)*136+n0+g];
                uint32_t b0l=Wl[(kb+t)*136+n0+g],b1l=Wl[(kb+t+4)*136+n0+g];
                mma16(c[nf],ahi,b0h,b1h);
                mma16(c[nf],alo,b0h,b1h);
                mma16(c[nf],ahi,b0l,b1l);
            }
        }

        int ra=r0+g,rb=r0+g+8;
        float da=(ra<n)?__ldg(dinv+ra):0.f;
        float db=(rb<n)?__ldg(dinv+rb):0.f;
        #pragma unroll
        for(int nf=0;nf<16;nf++){
            int col=nf*8+2*t;
            if(ra<n) *(float2*)(out+(size_t)ra*128+col)=make_float2(c[nf][0]*da,c[nf][1]*da);
            if(rb<n) *(float2*)(out+(size_t)rb*128+col)=make_float2(c[nf][2]*db,c[nf][3]*db);
        }
        __syncwarp();
    }
}

__global__ void rsqrt_kernel(float*d1,float*d2,int n){
    int i=blockIdx.x*blockDim.x+threadIdx.x;
    if(i<n){d1[i]=rsqrtf(d1[i]);d2[i]=rsqrtf(d2[i]);}
}

__global__ void scan_block_sums(const int* __restrict__ cnt,int* __restrict__ bsums,int n){
    __shared__ int wsum[32];
    int i=blockIdx.x*1024+threadIdx.x;
    int v=(i<n)?cnt[i]:0;
    #pragma unroll
    for(int o=16;o;o>>=1) v+=__shfl_down_sync(0xffffffffu,v,o);
    if((threadIdx.x&31)==0) wsum[threadIdx.x>>5]=v;
    __syncthreads();
    if(threadIdx.x<32){
        int s=wsum[threadIdx.x];
        #pragma unroll
        for(int o=16;o;o>>=1) s+=__shfl_down_sync(0xffffffffu,s,o);
        if(threadIdx.x==0) bsums[blockIdx.x]=s;
    }
}
__global__ void scan_bsums_excl(int*bsums,int nb){
    if(threadIdx.x==0&&blockIdx.x==0){
        int acc=0;
        for(int i=0;i<nb;i++){int t=bsums[i];bsums[i]=acc;acc+=t;}
    }
}
__global__ void scan_final(const int* __restrict__ cnt,const int* __restrict__ bsums,
                           int* __restrict__ base,int n){
    __shared__ int wsum[32];
    int i=blockIdx.x*1024+threadIdx.x;
    int v=(i<n)?cnt[i]:0;
    int lane=threadIdx.x&31,w=threadIdx.x>>5;
    int incl=v;
    #pragma unroll
    for(int o=1;o<32;o<<=1){int t=__shfl_up_sync(0xffffffffu,incl,o);if(lane>=o)incl+=t;}
    if(lane==31) wsum[w]=incl;
    __syncthreads();
    if(w==0){
        int s=wsum[lane];
        #pragma unroll
        for(int o=1;o<32;o<<=1){int t=__shfl_up_sync(0xffffffffu,s,o);if(lane>=o)s+=t;}
        __syncwarp();
        wsum[lane]=s;
    }
    __syncthreads();
    int prev=(w==0)?0:wsum[w-1];
    if(i<n) base[i]=incl-v+prev+bsums[blockIdx.x];
}

// ---------------------------------------------------------------------------
// Gather: out[i] = dinv[i] * ( h'[i] + sum_{s in CSR(i)} g[s]*h'[row[s]] )
__global__ void __launch_bounds__(256)
gather_kernel(const float* __restrict__ h,const float* __restrict__ dinv,
              const int* __restrict__ base,const int* __restrict__ cnt,
              const float2* __restrict__ edges,float* __restrict__ out,int n)
{
    int node=blockIdx.x*(blockDim.x>>5)+(threadIdx.x>>5);
    if(node>=n) return;
    int lane=threadIdx.x&31;
    float4 acc=__ldg((const float4*)(h+(size_t)node*128)+lane);
    int s=__ldg(base+node);
    int end=s+__ldg(cnt+node);
    for(;s+4<=end;s+=4){
        float2 e0=__ldg(edges+s),e1=__ldg(edges+s+1),e2=__ldg(edges+s+2),e3=__ldg(edges+s+3);
        int r0=__float_as_int(e0.x),r1=__float_as_int(e1.x),r2=__float_as_int(e2.x),r3=__float_as_int(e3.x);
        float4 v0=__ldg((const float4*)(h+(size_t)r0*128)+lane);
        float4 v1=__ldg((const float4*)(h+(size_t)r1*128)+lane);
        float4 v2=__ldg((const float4*)(h+(size_t)r2*128)+lane);
        float4 v3=__ldg((const float4*)(h+(size_t)r3*128)+lane);
        acc.x=fmaf(e0.y,v0.x,acc.x);acc.y=fmaf(e0.y,v0.y,acc.y);acc.z=fmaf(e0.y,v0.z,acc.z);acc.w=fmaf(e0.y,v0.w,acc.w);
        acc.x=fmaf(e1.y,v1.x,acc.x);acc.y=fmaf(e1.y,v1.y,acc.y);acc.z=fmaf(e1.y,v1.z,acc.z);acc.w=fmaf(e1.y,v1.w,acc.w);
        acc.x=fmaf(e2.y,v2.x,acc.x);acc.y=fmaf(e2.y,v2.y,acc.y);acc.z=fmaf(e2.y,v2.z,acc.z);acc.w=fmaf(e2.y,v2.w,acc.w);
        acc.x=fmaf(e3.y,v3.x,acc.x);acc.y=fmaf(e3.y,v3.y,acc.y);acc.z=fmaf(e3.y,v3.z,acc.z);acc.w=fmaf(e3.y,v3.w,acc.w);
    }
    for(;s<end;s++){
        float2 e0=__ldg(edges+s);
        int r0=__float_as_int(e0.x);
        float4 v0=__ldg((const float4*)(h+(size_t)r0*128)+lane);
        acc.x=fmaf(e0.y,v0.x,acc.x);acc.y=fmaf(e0.y,v0.y,acc.y);acc.z=fmaf(e0.y,v0.z,acc.z);acc.w=fmaf(e0.y,v0.w,acc.w);
    }
    float di=__ldg(dinv+node);
    acc.x*=di;acc.y*=di;acc.z*=di;acc.w*=di;
    ((float4*)(out+(size_t)node*128))[lane]=acc;
}

extern "C" void kernel_launch(void* const* d_in,const int* in_sizes,int n_in,
                              void* d_out,int out_size)
{
    const float* x=(const float*)d_in[0];
    const int*   ei=(const int*)d_in[1];
    const float* ea=(const float*)d_in[2];
    const float* W1=(const float*)d_in[3];
    const float* m1w1=(const float*)d_in[4];
    const float* m1b1=(const float*)d_in[5];
    const float* m1w2=(const float*)d_in[6];
    const float* m1b2=(const float*)d_in[7];
    const float* W2=(const float*)d_in[8];
    const float* m2w1=(const float*)d_in[9];
    const float* m2b1=(const float*)d_in[10];
    const float* m2w2=(const float*)d_in[11];
    const float* m2b2=(const float*)d_in[12];
    float* out=(float*)d_out;

    int n=in_sizes[0]/128;
    int E=in_sizes[1]/2;
    const int* rows=ei;
    const int* cols=ei+E;
    int nblk=(n+1023)/1024;

    float *ph,*pagg,*pd1,*pd2;
    float2 *pe1,*pe2;
    int *pcnt,*pcur,*pbase,*pbsums;
    cudaGetSymbolAddress((void**)&ph,g_h);
    cudaGetSymbolAddress((void**)&pagg,g_agg);
    cudaGetSymbolAddress((void**)&pd1,g_d1);
    cudaGetSymbolAddress((void**)&pd2,g_d2);
    cudaGetSymbolAddress((void**)&pcnt,g_cnt);
    cudaGetSymbolAddress((void**)&pcur,g_cur);
    cudaGetSymbolAddress((void**)&pbase,g_base);
    cudaGetSymbolAddress((void**)&pbsums,g_bsums);
    cudaGetSymbolAddress((void**)&pe1,g_e1);
    cudaGetSymbolAddress((void**)&pe2,g_e2);

    const int GATE_SMEM=4864*4;                  // 19456 B
    const int GEMM_SMEM=(17408+8*16*132)*4;      // 137216 B
    cudaFuncSetAttribute(gate_mma_kernel,cudaFuncAttributeMaxDynamicSharedMemorySize,GATE_SMEM);
    cudaFuncSetAttribute(gemm_mma_kernel,cudaFuncAttributeMaxDynamicSharedMemorySize,GEMM_SMEM);

    // CSR layout first (depends only on cols), then gate writes slots directly.
    init_kernel<<<(n+255)/256,256>>>(pd1,pd2,pcnt,pcur,n);
    hist_kernel<<<(E+255)/256,256>>>(cols,pcnt,E);
    scan_block_sums<<<nblk,1024>>>(pcnt,pbsums,n);
    scan_bsums_excl<<<1,32>>>(pbsums,nblk);
    scan_final<<<nblk,1024>>>(pcnt,pbsums,pbase,n);

    gate_mma_kernel<<<296,256,GATE_SMEM>>>(ea,m1w1,m1b1,m1w2,m1b2,m2w1,m2b1,m2w2,m2b2,
                                           rows,cols,pbase,pcur,pe1,pe2,pd1,pd2,E);
    rsqrt_kernel<<<(n+255)/256,256>>>(pd1,pd2,n);

    gemm_mma_kernel<<<148,256,GEMM_SMEM>>>(x,W1,pd1,ph,n,0);
    gather_kernel<<<(n+7)/8,256>>>(ph,pd1,pbase,pcnt,pe1,pagg,n);

    gemm_mma_kernel<<<148,256,GEMM_SMEM>>>(pagg,W2,pd2,ph,n,1);
    gather_kernel<<<(n+7)/8,256>>>(ph,pd2,pbase,pcnt,pe2,out,n);
}

// round 12
// speedup vs baseline: 1.8056x; 1.0229x over previous
#include <cuda_runtime.h>
#include <cuda_bf16.h>
#include <math.h>
#include <cstdint>

#define MAXN 100000
#define MAXE 1600000
#define NBLK 98

// bf16 m16n8k16 mma (sm_80+ PTX)
__device__ __forceinline__ void mma16(float* c,const uint32_t* a,uint32_t b0,uint32_t b1){
    asm volatile("mma.sync.aligned.m16n8k16.row.col.f32.bf16.bf16.f32 "
                 "{%0,%1,%2,%3},{%4,%5,%6,%7},{%8,%9},{%0,%1,%2,%3};"
        :"+f"(c[0]),"+f"(c[1]),"+f"(c[2]),"+f"(c[3])
        :"r"(a[0]),"r"(a[1]),"r"(a[2]),"r"(a[3]),"r"(b0),"r"(b1));
}
// packed split: (x0,x1) -> bf16x2 hi + bf16x2 residual (x0 in low half)
__device__ __forceinline__ void split2(float x0,float x1,uint32_t&hi,uint32_t&lo){
    __nv_bfloat162 h=__floats2bfloat162_rn(x0,x1);
    hi=reinterpret_cast<uint32_t&>(h);
    float2 f=__bfloat1622float2(h);
    __nv_bfloat162 l=__floats2bfloat162_rn(x0-f.x,x1-f.y);
    lo=reinterpret_cast<uint32_t&>(l);
}

__device__ float  g_h[(size_t)MAXN*128];    // h' = dinv[r]*(X@W)[r]
__device__ float  g_agg[(size_t)MAXN*128];
__device__ float  g_d1[MAXN];
__device__ float  g_d2[MAXN];
__device__ int    g_cnt[MAXN];
__device__ int    g_cur[MAXN];
__device__ int    g_base[MAXN];
__device__ int    g_bsums[NBLK+1];
__device__ float2 g_e1[MAXE];               // CSR slot: {row(bits), g1}
__device__ float2 g_e2[MAXE];               // CSR slot: {row(bits), g2}

__global__ void zero_cnt_kernel(int*cnt,int n){
    int i=blockIdx.x*blockDim.x+threadIdx.x;
    if(i<n) cnt[i]=0;
}
__global__ void hist_kernel(const int* __restrict__ cols,int* __restrict__ cnt,int E){
    int e=blockIdx.x*blockDim.x+threadIdx.x;
    if(e<E) atomicAdd(cnt+__ldg(cols+e),1);
}

// ---------------------------------------------------------------------------
// Gate: bf16 3-term split MMA (K=16 in one chunk). Writes CSR records directly.
__global__ void __launch_bounds__(256) gate_mma_kernel(
    const float* __restrict__ ea,
    const float* __restrict__ m1w1,const float* __restrict__ m1b1,
    const float* __restrict__ m1w2,const float* __restrict__ m1b2,
    const float* __restrict__ m2w1,const float* __restrict__ m2b1,
    const float* __restrict__ m2w2,const float* __restrict__ m2b2,
    const int* __restrict__ rows,const int* __restrict__ cols,
    const int* __restrict__ base,int* __restrict__ cur,
    float2* __restrict__ e1,float2* __restrict__ e2,
    float* __restrict__ deg1,float* __restrict__ deg2,int E)
{
    extern __shared__ float ds[];
    uint32_t* dsu=(uint32_t*)ds;
    float* biasp=ds+4352;
    float* w2p  =ds+4608;
    int tid=threadIdx.x;

    for(int idx=tid;idx<2048;idx+=256){
        int layer=idx>>10,rem=idx&1023,k2=rem>>7,n=rem&127;
        const float* W=layer?m2w1:m1w1;
        float w0=__ldg(W+(2*k2)*128+n),w1=__ldg(W+(2*k2+1)*128+n);
        uint32_t hi,lo; split2(w0,w1,hi,lo);
        dsu[layer*2176+k2*136+n]=hi;
        dsu[layer*2176+1088+k2*136+n]=lo;
    }
    if(tid<256){
        biasp[tid]=(tid<128)?__ldg(m1b1+tid):__ldg(m2b1+tid-128);
        w2p[tid]  =(tid<128)?__ldg(m1w2+tid):__ldg(m2w2+tid-128);
    }
    __syncthreads();

    int lane=tid&31,g=lane>>2,t=lane&3;
    int w=blockIdx.x*(blockDim.x>>5)+(tid>>5);
    int nwarps=gridDim.x*(blockDim.x>>5);
    int ntask=(E+63)>>6;
    float b2v[2]={__ldg(m1b2),__ldg(m2b2)};

    for(int task=w;task<ntask;task+=nwarps){
        int e0=task*64;
        uint32_t Ahi[4][4],Alo[4][4];
        #pragma unroll
        for(int mt=0;mt<4;mt++){
            int r1=e0+mt*16+g,r2=r1+8;
            float2 z=make_float2(0.f,0.f);
            float2 v1a=(r1<E)?*(const float2*)(ea+(size_t)r1*16+2*t):z;
            float2 v1b=(r1<E)?*(const float2*)(ea+(size_t)r1*16+8+2*t):z;
            float2 v2a=(r2<E)?*(const float2*)(ea+(size_t)r2*16+2*t):z;
            float2 v2b=(r2<E)?*(const float2*)(ea+(size_t)r2*16+8+2*t):z;
            split2(v1a.x,v1a.y,Ahi[mt][0],Alo[mt][0]);
            split2(v2a.x,v2a.y,Ahi[mt][1],Alo[mt][1]);
            split2(v1b.x,v1b.y,Ahi[mt][2],Alo[mt][2]);
            split2(v2b.x,v2b.y,Ahi[mt][3],Alo[mt][3]);
        }
        int slotA[4]={-1,-1,-1,-1},slotB[4]={-1,-1,-1,-1};
        #pragma unroll
        for(int layer=0;layer<2;layer++){
            const uint32_t* Bh=dsu+layer*2176;
            const uint32_t* Bl=Bh+1088;
            const float* biasl=biasp+layer*128;
            const float* w2l=w2p+layer*128;
            float p0[4]={0,0,0,0},p1[4]={0,0,0,0};
            #pragma unroll 2
            for(int nt=0;nt<16;nt++){
                int n0=nt*8;
                float bA=biasl[n0+2*t],bB=biasl[n0+2*t+1];
                float c[4][4];
                #pragma unroll
                for(int mt=0;mt<4;mt++){c[mt][0]=bA;c[mt][1]=bB;c[mt][2]=bA;c[mt][3]=bB;}
                uint32_t b0h=Bh[t*136+n0+g],b1h=Bh[(t+4)*136+n0+g];
                uint32_t b0l=Bl[t*136+n0+g],b1l=Bl[(t+4)*136+n0+g];
                #pragma unroll
                for(int mt=0;mt<4;mt++){
                    mma16(c[mt],Ahi[mt],b0h,b1h);
                    mma16(c[mt],Alo[mt],b0h,b1h);
                    mma16(c[mt],Ahi[mt],b0l,b1l);
                }
                float wA=w2l[n0+2*t],wB=w2l[n0+2*t+1];
                #pragma unroll
                for(int mt=0;mt<4;mt++){
                    p0[mt]+=fmaxf(c[mt][0],0.f)*wA+fmaxf(c[mt][1],0.f)*wB;
                    p1[mt]+=fmaxf(c[mt][2],0.f)*wA+fmaxf(c[mt][3],0.f)*wB;
                }
            }
            #pragma unroll
            for(int mt=0;mt<4;mt++){
                p0[mt]+=__shfl_xor_sync(0xffffffffu,p0[mt],1);
                p0[mt]+=__shfl_xor_sync(0xffffffffu,p0[mt],2);
                p1[mt]+=__shfl_xor_sync(0xffffffffu,p1[mt],1);
                p1[mt]+=__shfl_xor_sync(0xffffffffu,p1[mt],2);
            }
            if(t==0){
                float b2=b2v[layer];
                #pragma unroll
                for(int mt=0;mt<4;mt++){
                    int e=e0+mt*16+g,e2i=e+8;
                    if(layer==0){
                        if(e<E){
                            float gg=1.0f/(1.0f+expf(-(p0[mt]+b2)));
                            int c_=__ldg(cols+e),r_=__ldg(rows+e);
                            int slot=__ldg(base+c_)+atomicAdd(cur+c_,1);
                            slotA[mt]=slot;
                            e1[slot]=make_float2(__int_as_float(r_),gg);
                            atomicAdd(deg1+c_,gg);
                        }
                        if(e2i<E){
                            float gg=1.0f/(1.0f+expf(-(p1[mt]+b2)));
                            int c_=__ldg(cols+e2i),r_=__ldg(rows+e2i);
                            int slot=__ldg(base+c_)+atomicAdd(cur+c_,1);
                            slotB[mt]=slot;
                            e1[slot]=make_float2(__int_as_float(r_),gg);
                            atomicAdd(deg1+c_,gg);
                        }
                    }else{
                        if(slotA[mt]>=0){
                            float gg=1.0f/(1.0f+expf(-(p0[mt]+b2)));
                            int c_=__ldg(cols+e),r_=__ldg(rows+e);
                            e2[slotA[mt]]=make_float2(__int_as_float(r_),gg);
                            atomicAdd(deg2+c_,gg);
                        }
                        if(slotB[mt]>=0){
                            float gg=1.0f/(1.0f+expf(-(p1[mt]+b2)));
                            int c_=__ldg(cols+e2i),r_=__ldg(rows+e2i);
                            e2[slotB[mt]]=make_float2(__int_as_float(r_),gg);
                            atomicAdd(deg2+c_,gg);
                        }
                    }
                }
            }
        }
    }
}

// ---------------------------------------------------------------------------
// Dense GEMM: bf16 3-term split, K=16 chunks; epilogue scales row by dinv[r].
__global__ void __launch_bounds__(256) gemm_mma_kernel(
    const float* __restrict__ X,const float* __restrict__ W,
    const float* __restrict__ dinv,
    float* __restrict__ out,int n,int relu_in)
{
    extern __shared__ float sm[];
    uint32_t* Wh=(uint32_t*)sm;       // 8704
    uint32_t* Wl=Wh+8704;             // 8704
    float* Xs=sm+17408;
    int tid=threadIdx.x,wid=tid>>5,lane=tid&31;
    int g=lane>>2,t=lane&3;

    for(int idx=tid;idx<8192;idx+=256){
        int k2=idx>>7,nn=idx&127;
        float w0=__ldg(W+(2*k2)*128+nn),w1=__ldg(W+(2*k2+1)*128+nn);
        uint32_t hi,lo; split2(w0,w1,hi,lo);
        Wh[k2*136+nn]=hi; Wl[k2*136+nn]=lo;
    }
    __syncthreads();

    float* Xw=Xs+wid*(16*132);
    int ntiles=(n+127)>>7;
    for(int tile=blockIdx.x;tile<ntiles;tile+=gridDim.x){
        int r0=tile*128+wid*16;
        #pragma unroll 4
        for(int i=0;i<16;i++){
            int r=r0+i;
            float4 v=make_float4(0.f,0.f,0.f,0.f);
            if(r<n) v=__ldg((const float4*)(X+(size_t)r*128)+lane);
            if(relu_in){v.x=fmaxf(v.x,0.f);v.y=fmaxf(v.y,0.f);v.z=fmaxf(v.z,0.f);v.w=fmaxf(v.w,0.f);}
            float* d=Xw+i*132+lane*4;
            d[0]=v.x;d[1]=v.y;d[2]=v.z;d[3]=v.w;
        }
        __syncwarp();

        float c[16][4];
        #pragma unroll
        for(int nf=0;nf<16;nf++){c[nf][0]=0.f;c[nf][1]=0.f;c[nf][2]=0.f;c[nf][3]=0.f;}

        #pragma unroll 1
        for(int ks=0;ks<8;ks++){
            int k0=ks*16,kb=ks*8;
            float2 xa=*(const float2*)(Xw+g*132+k0+2*t);
            float2 xb=*(const float2*)(Xw+(g+8)*132+k0+2*t);
            float2 xc=*(const float2*)(Xw+g*132+k0+8+2*t);
            float2 xd=*(const float2*)(Xw+(g+8)*132+k0+8+2*t);
            uint32_t ahi[4],alo[4];
            split2(xa.x,xa.y,ahi[0],alo[0]);
            split2(xb.x,xb.y,ahi[1],alo[1]);
            split2(xc.x,xc.y,ahi[2],alo[2]);
            split2(xd.x,xd.y,ahi[3],alo[3]);
            #pragma unroll
            for(int nf=0;nf<16;nf++){
                int n0=nf*8;
                uint32_t b0h=Wh[(kb+t)*136+n0+g],b1h=Wh[(kb+t+4)*136+n0+g];
                uint32_t b0l=Wl[(kb+t)*136+n0+g],b1l=Wl[(kb+t+4)*136+n0+g];
                mma16(c[nf],ahi,b0h,b1h);
                mma16(c[nf],alo,b0h,b1h);
                mma16(c[nf],ahi,b0l,b1l);
            }
        }

        int ra=r0+g,rb=r0+g+8;
        float da=(ra<n)?__ldg(dinv+ra):0.f;
        float db=(rb<n)?__ldg(dinv+rb):0.f;
        #pragma unroll
        for(int nf=0;nf<16;nf++){
            int col=nf*8+2*t;
            if(ra<n) *(float2*)(out+(size_t)ra*128+col)=make_float2(c[nf][0]*da,c[nf][1]*da);
            if(rb<n) *(float2*)(out+(size_t)rb*128+col)=make_float2(c[nf][2]*db,c[nf][3]*db);
        }
        __syncwarp();
    }
}

__global__ void rsqrt_kernel(float*d1,float*d2,int n){
    int i=blockIdx.x*blockDim.x+threadIdx.x;
    if(i<n){d1[i]=rsqrtf(d1[i]);d2[i]=rsqrtf(d2[i]);}
}

__global__ void scan_block_sums(const int* __restrict__ cnt,int* __restrict__ bsums,int n){
    __shared__ int wsum[32];
    int i=blockIdx.x*1024+threadIdx.x;
    int v=(i<n)?cnt[i]:0;
    #pragma unroll
    for(int o=16;o;o>>=1) v+=__shfl_down_sync(0xffffffffu,v,o);
    if((threadIdx.x&31)==0) wsum[threadIdx.x>>5]=v;
    __syncthreads();
    if(threadIdx.x<32){
        int s=wsum[threadIdx.x];
        #pragma unroll
        for(int o=16;o;o>>=1) s+=__shfl_down_sync(0xffffffffu,s,o);
        if(threadIdx.x==0) bsums[blockIdx.x]=s;
    }
}
// scan_final also computes its block offset (sum of prior bsums) and fuses
// the d1/d2/cur initialization — removes two kernel launches.
__global__ void scan_final(const int* __restrict__ cnt,const int* __restrict__ bsums,
                           int* __restrict__ base,float* __restrict__ d1,
                           float* __restrict__ d2,int* __restrict__ cur,int n){
    __shared__ int wsum[32];
    __shared__ int boff;
    int tid=threadIdx.x;
    if(tid==0) boff=0;
    __syncthreads();
    if(tid<(int)blockIdx.x) atomicAdd(&boff,__ldg(bsums+tid));  // gridDim<=98<1024
    int i=blockIdx.x*1024+tid;
    int v=(i<n)?cnt[i]:0;
    int lane=tid&31,w=tid>>5;
    int incl=v;
    #pragma unroll
    for(int o=1;o<32;o<<=1){int t=__shfl_up_sync(0xffffffffu,incl,o);if(lane>=o)incl+=t;}
    if(lane==31) wsum[w]=incl;
    __syncthreads();
    if(w==0){
        int s=wsum[lane];
        #pragma unroll
        for(int o=1;o<32;o<<=1){int t=__shfl_up_sync(0xffffffffu,s,o);if(lane>=o)s+=t;}
        __syncwarp();
        wsum[lane]=s;
    }
    __syncthreads();
    int prev=(w==0)?0:wsum[w-1];
    if(i<n){
        base[i]=incl-v+prev+boff;
        d1[i]=1.0f; d2[i]=1.0f; cur[i]=0;
    }
}

// ---------------------------------------------------------------------------
// Gather: out[i] = dinv[i] * ( h'[i] + sum_{s in CSR(i)} g[s]*h'[row[s]] )
__global__ void __launch_bounds__(256)
gather_kernel(const float* __restrict__ h,const float* __restrict__ dinv,
              const int* __restrict__ base,const int* __restrict__ cnt,
              const float2* __restrict__ edges,float* __restrict__ out,int n)
{
    int node=blockIdx.x*(blockDim.x>>5)+(threadIdx.x>>5);
    if(node>=n) return;
    int lane=threadIdx.x&31;
    float4 acc=__ldg((const float4*)(h+(size_t)node*128)+lane);
    int s=__ldg(base+node);
    int end=s+__ldg(cnt+node);
    for(;s+4<=end;s+=4){
        float2 e0=__ldg(edges+s),e1=__ldg(edges+s+1),e2=__ldg(edges+s+2),e3=__ldg(edges+s+3);
        int r0=__float_as_int(e0.x),r1=__float_as_int(e1.x),r2=__float_as_int(e2.x),r3=__float_as_int(e3.x);
        float4 v0=__ldg((const float4*)(h+(size_t)r0*128)+lane);
        float4 v1=__ldg((const float4*)(h+(size_t)r1*128)+lane);
        float4 v2=__ldg((const float4*)(h+(size_t)r2*128)+lane);
        float4 v3=__ldg((const float4*)(h+(size_t)r3*128)+lane);
        acc.x=fmaf(e0.y,v0.x,acc.x);acc.y=fmaf(e0.y,v0.y,acc.y);acc.z=fmaf(e0.y,v0.z,acc.z);acc.w=fmaf(e0.y,v0.w,acc.w);
        acc.x=fmaf(e1.y,v1.x,acc.x);acc.y=fmaf(e1.y,v1.y,acc.y);acc.z=fmaf(e1.y,v1.z,acc.z);acc.w=fmaf(e1.y,v1.w,acc.w);
        acc.x=fmaf(e2.y,v2.x,acc.x);acc.y=fmaf(e2.y,v2.y,acc.y);acc.z=fmaf(e2.y,v2.z,acc.z);acc.w=fmaf(e2.y,v2.w,acc.w);
        acc.x=fmaf(e3.y,v3.x,acc.x);acc.y=fmaf(e3.y,v3.y,acc.y);acc.z=fmaf(e3.y,v3.z,acc.z);acc.w=fmaf(e3.y,v3.w,acc.w);
    }
    for(;s<end;s++){
        float2 e0=__ldg(edges+s);
        int r0=__float_as_int(e0.x);
        float4 v0=__ldg((const float4*)(h+(size_t)r0*128)+lane);
        acc.x=fmaf(e0.y,v0.x,acc.x);acc.y=fmaf(e0.y,v0.y,acc.y);acc.z=fmaf(e0.y,v0.z,acc.z);acc.w=fmaf(e0.y,v0.w,acc.w);
    }
    float di=__ldg(dinv+node);
    acc.x*=di;acc.y*=di;acc.z*=di;acc.w*=di;
    ((float4*)(out+(size_t)node*128))[lane]=acc;
}

extern "C" void kernel_launch(void* const* d_in,const int* in_sizes,int n_in,
                              void* d_out,int out_size)
{
    const float* x=(const float*)d_in[0];
    const int*   ei=(const int*)d_in[1];
    const float* ea=(const float*)d_in[2];
    const float* W1=(const float*)d_in[3];
    const float* m1w1=(const float*)d_in[4];
    const float* m1b1=(const float*)d_in[5];
    const float* m1w2=(const float*)d_in[6];
    const float* m1b2=(const float*)d_in[7];
    const float* W2=(const float*)d_in[8];
    const float* m2w1=(const float*)d_in[9];
    const float* m2b1=(const float*)d_in[10];
    const float* m2w2=(const float*)d_in[11];
    const float* m2b2=(const float*)d_in[12];
    float* out=(float*)d_out;

    int n=in_sizes[0]/128;
    int E=in_sizes[1]/2;
    const int* rows=ei;
    const int* cols=ei+E;
    int nblk=(n+1023)/1024;

    float *ph,*pagg,*pd1,*pd2;
    float2 *pe1,*pe2;
    int *pcnt,*pcur,*pbase,*pbsums;
    cudaGetSymbolAddress((void**)&ph,g_h);
    cudaGetSymbolAddress((void**)&pagg,g_agg);
    cudaGetSymbolAddress((void**)&pd1,g_d1);
    cudaGetSymbolAddress((void**)&pd2,g_d2);
    cudaGetSymbolAddress((void**)&pcnt,g_cnt);
    cudaGetSymbolAddress((void**)&pcur,g_cur);
    cudaGetSymbolAddress((void**)&pbase,g_base);
    cudaGetSymbolAddress((void**)&pbsums,g_bsums);
    cudaGetSymbolAddress((void**)&pe1,g_e1);
    cudaGetSymbolAddress((void**)&pe2,g_e2);

    const int GATE_SMEM=4864*4;                  // 19456 B
    const int GEMM_SMEM=(17408+8*16*132)*4;      // 137216 B
    cudaFuncSetAttribute(gate_mma_kernel,cudaFuncAttributeMaxDynamicSharedMemorySize,GATE_SMEM);
    cudaFuncSetAttribute(gemm_mma_kernel,cudaFuncAttributeMaxDynamicSharedMemorySize,GEMM_SMEM);

    // Front-end: CSR layout (cols only); scan_final also inits d1/d2/cur.
    zero_cnt_kernel<<<(n+255)/256,256>>>(pcnt,n);
    hist_kernel<<<(E+255)/256,256>>>(cols,pcnt,E);
    scan_block_sums<<<nblk,1024>>>(pcnt,pbsums,n);
    scan_final<<<nblk,1024>>>(pcnt,pbsums,pbase,pd1,pd2,pcur,n);

    gate_mma_kernel<<<296,256,GATE_SMEM>>>(ea,m1w1,m1b1,m1w2,m1b2,m2w1,m2b1,m2w2,m2b2,
                                           rows,cols,pbase,pcur,pe1,pe2,pd1,pd2,E);
    rsqrt_kernel<<<(n+255)/256,256>>>(pd1,pd2,n);

    gemm_mma_kernel<<<148,256,GEMM_SMEM>>>(x,W1,pd1,ph,n,0);
    gather_kernel<<<(n+7)/8,256>>>(ph,pd1,pbase,pcnt,pe1,pagg,n);

    gemm_mma_kernel<<<148,256,GEMM_SMEM>>>(pagg,W2,pd2,ph,n,1);
    gather_kernel<<<(n+7)/8,256>>>(ph,pd2,pbase,pcnt,pe2,out,n);
}

// round 13
// speedup vs baseline: 1.8809x; 1.0417x over previous
#include <cuda_runtime.h>
#include <cuda_bf16.h>
#include <cuda_fp16.h>
#include <math.h>
#include <cstdint>

#define MAXN 100000
#define MAXE 1600000
#define NBLK 98

// bf16 m16n8k16 mma (sm_80+ PTX)
__device__ __forceinline__ void mma16(float* c,const uint32_t* a,uint32_t b0,uint32_t b1){
    asm volatile("mma.sync.aligned.m16n8k16.row.col.f32.bf16.bf16.f32 "
                 "{%0,%1,%2,%3},{%4,%5,%6,%7},{%8,%9},{%0,%1,%2,%3};"
        :"+f"(c[0]),"+f"(c[1]),"+f"(c[2]),"+f"(c[3])
        :"r"(a[0]),"r"(a[1]),"r"(a[2]),"r"(a[3]),"r"(b0),"r"(b1));
}
// packed split: (x0,x1) -> bf16x2 hi + bf16x2 residual
__device__ __forceinline__ void split2(float x0,float x1,uint32_t&hi,uint32_t&lo){
    __nv_bfloat162 h=__floats2bfloat162_rn(x0,x1);
    hi=reinterpret_cast<uint32_t&>(h);
    float2 f=__bfloat1622float2(h);
    __nv_bfloat162 l=__floats2bfloat162_rn(x0-f.x,x1-f.y);
    lo=reinterpret_cast<uint32_t&>(l);
}
// unpack 4 halves (uint2) -> float4
__device__ __forceinline__ float4 h4(uint2 u){
    __half2 a=*reinterpret_cast<__half2*>(&u.x);
    __half2 b=*reinterpret_cast<__half2*>(&u.y);
    float2 fa=__half22float2(a),fb=__half22float2(b);
    return make_float4(fa.x,fa.y,fb.x,fb.y);
}

__device__ float  g_h[(size_t)MAXN*128];    // h' fp32 (self term + gemm2 input)
__device__ __half g_hh[(size_t)MAXN*128];   // h' fp16 shadow (neighbor gathers)
__device__ float  g_agg[(size_t)MAXN*128];
__device__ float  g_d1[MAXN];
__device__ float  g_d2[MAXN];
__device__ int    g_cnt[MAXN];
__device__ int    g_cur[MAXN];
__device__ int    g_base[MAXN];
__device__ int    g_bsums[NBLK+1];
__device__ float2 g_e1[MAXE];               // CSR slot: {row(bits), g1}
__device__ float2 g_e2[MAXE];               // CSR slot: {row(bits), g2}

__global__ void zero_cnt_kernel(int*cnt,int n){
    int i=blockIdx.x*blockDim.x+threadIdx.x;
    if(i<n) cnt[i]=0;
}
__global__ void hist_kernel(const int* __restrict__ cols,int* __restrict__ cnt,int E){
    int e=blockIdx.x*blockDim.x+threadIdx.x;
    if(e<E) atomicAdd(cnt+__ldg(cols+e),1);
}

// ---------------------------------------------------------------------------
// Gate: bf16 3-term split MMA. Writes CSR records directly.
__global__ void __launch_bounds__(256) gate_mma_kernel(
    const float* __restrict__ ea,
    const float* __restrict__ m1w1,const float* __restrict__ m1b1,
    const float* __restrict__ m1w2,const float* __restrict__ m1b2,
    const float* __restrict__ m2w1,const float* __restrict__ m2b1,
    const float* __restrict__ m2w2,const float* __restrict__ m2b2,
    const int* __restrict__ rows,const int* __restrict__ cols,
    const int* __restrict__ base,int* __restrict__ cur,
    float2* __restrict__ e1,float2* __restrict__ e2,
    float* __restrict__ deg1,float* __restrict__ deg2,int E)
{
    extern __shared__ float ds[];
    uint32_t* dsu=(uint32_t*)ds;
    float* biasp=ds+4352;
    float* w2p  =ds+4608;
    int tid=threadIdx.x;

    for(int idx=tid;idx<2048;idx+=256){
        int layer=idx>>10,rem=idx&1023,k2=rem>>7,n=rem&127;
        const float* W=layer?m2w1:m1w1;
        float w0=__ldg(W+(2*k2)*128+n),w1=__ldg(W+(2*k2+1)*128+n);
        uint32_t hi,lo; split2(w0,w1,hi,lo);
        dsu[layer*2176+k2*136+n]=hi;
        dsu[layer*2176+1088+k2*136+n]=lo;
    }
    if(tid<256){
        biasp[tid]=(tid<128)?__ldg(m1b1+tid):__ldg(m2b1+tid-128);
        w2p[tid]  =(tid<128)?__ldg(m1w2+tid):__ldg(m2w2+tid-128);
    }
    __syncthreads();

    int lane=tid&31,g=lane>>2,t=lane&3;
    int w=blockIdx.x*(blockDim.x>>5)+(tid>>5);
    int nwarps=gridDim.x*(blockDim.x>>5);
    int ntask=(E+63)>>6;
    float b2v[2]={__ldg(m1b2),__ldg(m2b2)};

    for(int task=w;task<ntask;task+=nwarps){
        int e0=task*64;
        uint32_t Ahi[4][4],Alo[4][4];
        #pragma unroll
        for(int mt=0;mt<4;mt++){
            int r1=e0+mt*16+g,r2=r1+8;
            float2 z=make_float2(0.f,0.f);
            float2 v1a=(r1<E)?*(const float2*)(ea+(size_t)r1*16+2*t):z;
            float2 v1b=(r1<E)?*(const float2*)(ea+(size_t)r1*16+8+2*t):z;
            float2 v2a=(r2<E)?*(const float2*)(ea+(size_t)r2*16+2*t):z;
            float2 v2b=(r2<E)?*(const float2*)(ea+(size_t)r2*16+8+2*t):z;
            split2(v1a.x,v1a.y,Ahi[mt][0],Alo[mt][0]);
            split2(v2a.x,v2a.y,Ahi[mt][1],Alo[mt][1]);
            split2(v1b.x,v1b.y,Ahi[mt][2],Alo[mt][2]);
            split2(v2b.x,v2b.y,Ahi[mt][3],Alo[mt][3]);
        }
        int slotA[4]={-1,-1,-1,-1},slotB[4]={-1,-1,-1,-1};
        #pragma unroll
        for(int layer=0;layer<2;layer++){
            const uint32_t* Bh=dsu+layer*2176;
            const uint32_t* Bl=Bh+1088;
            const float* biasl=biasp+layer*128;
            const float* w2l=w2p+layer*128;
            float p0[4]={0,0,0,0},p1[4]={0,0,0,0};
            #pragma unroll 2
            for(int nt=0;nt<16;nt++){
                int n0=nt*8;
                float bA=biasl[n0+2*t],bB=biasl[n0+2*t+1];
                float c[4][4];
                #pragma unroll
                for(int mt=0;mt<4;mt++){c[mt][0]=bA;c[mt][1]=bB;c[mt][2]=bA;c[mt][3]=bB;}
                uint32_t b0h=Bh[t*136+n0+g],b1h=Bh[(t+4)*136+n0+g];
                uint32_t b0l=Bl[t*136+n0+g],b1l=Bl[(t+4)*136+n0+g];
                #pragma unroll
                for(int mt=0;mt<4;mt++){
                    mma16(c[mt],Ahi[mt],b0h,b1h);
                    mma16(c[mt],Alo[mt],b0h,b1h);
                    mma16(c[mt],Ahi[mt],b0l,b1l);
                }
                float wA=w2l[n0+2*t],wB=w2l[n0+2*t+1];
                #pragma unroll
                for(int mt=0;mt<4;mt++){
                    p0[mt]+=fmaxf(c[mt][0],0.f)*wA+fmaxf(c[mt][1],0.f)*wB;
                    p1[mt]+=fmaxf(c[mt][2],0.f)*wA+fmaxf(c[mt][3],0.f)*wB;
                }
            }
            #pragma unroll
            for(int mt=0;mt<4;mt++){
                p0[mt]+=__shfl_xor_sync(0xffffffffu,p0[mt],1);
                p0[mt]+=__shfl_xor_sync(0xffffffffu,p0[mt],2);
                p1[mt]+=__shfl_xor_sync(0xffffffffu,p1[mt],1);
                p1[mt]+=__shfl_xor_sync(0xffffffffu,p1[mt],2);
            }
            if(t==0){
                float b2=b2v[layer];
                #pragma unroll
                for(int mt=0;mt<4;mt++){
                    int e=e0+mt*16+g,e2i=e+8;
                    if(layer==0){
                        if(e<E){
                            float gg=1.0f/(1.0f+expf(-(p0[mt]+b2)));
                            int c_=__ldg(cols+e),r_=__ldg(rows+e);
                            int slot=__ldg(base+c_)+atomicAdd(cur+c_,1);
                            slotA[mt]=slot;
                            e1[slot]=make_float2(__int_as_float(r_),gg);
                            atomicAdd(deg1+c_,gg);
                        }
                        if(e2i<E){
                            float gg=1.0f/(1.0f+expf(-(p1[mt]+b2)));
                            int c_=__ldg(cols+e2i),r_=__ldg(rows+e2i);
                            int slot=__ldg(base+c_)+atomicAdd(cur+c_,1);
                            slotB[mt]=slot;
                            e1[slot]=make_float2(__int_as_float(r_),gg);
                            atomicAdd(deg1+c_,gg);
                        }
                    }else{
                        if(slotA[mt]>=0){
                            float gg=1.0f/(1.0f+expf(-(p0[mt]+b2)));
                            int c_=__ldg(cols+e),r_=__ldg(rows+e);
                            e2[slotA[mt]]=make_float2(__int_as_float(r_),gg);
                            atomicAdd(deg2+c_,gg);
                        }
                        if(slotB[mt]>=0){
                            float gg=1.0f/(1.0f+expf(-(p1[mt]+b2)));
                            int c_=__ldg(cols+e2i),r_=__ldg(rows+e2i);
                            e2[slotB[mt]]=make_float2(__int_as_float(r_),gg);
                            atomicAdd(deg2+c_,gg);
                        }
                    }
                }
            }
        }
    }
}

// ---------------------------------------------------------------------------
// Dense GEMM: bf16 3-term split; epilogue scales by dinv[r], writes fp32 h
// AND fp16 shadow hh.
__global__ void __launch_bounds__(256) gemm_mma_kernel(
    const float* __restrict__ X,const float* __restrict__ W,
    const float* __restrict__ dinv,
    float* __restrict__ out,__half* __restrict__ hh,int n,int relu_in)
{
    extern __shared__ float sm[];
    uint32_t* Wh=(uint32_t*)sm;
    uint32_t* Wl=Wh+8704;
    float* Xs=sm+17408;
    int tid=threadIdx.x,wid=tid>>5,lane=tid&31;
    int g=lane>>2,t=lane&3;

    for(int idx=tid;idx<8192;idx+=256){
        int k2=idx>>7,nn=idx&127;
        float w0=__ldg(W+(2*k2)*128+nn),w1=__ldg(W+(2*k2+1)*128+nn);
        uint32_t hi,lo; split2(w0,w1,hi,lo);
        Wh[k2*136+nn]=hi; Wl[k2*136+nn]=lo;
    }
    __syncthreads();

    float* Xw=Xs+wid*(16*132);
    int ntiles=(n+127)>>7;
    for(int tile=blockIdx.x;tile<ntiles;tile+=gridDim.x){
        int r0=tile*128+wid*16;
        #pragma unroll 4
        for(int i=0;i<16;i++){
            int r=r0+i;
            float4 v=make_float4(0.f,0.f,0.f,0.f);
            if(r<n) v=__ldg((const float4*)(X+(size_t)r*128)+lane);
            if(relu_in){v.x=fmaxf(v.x,0.f);v.y=fmaxf(v.y,0.f);v.z=fmaxf(v.z,0.f);v.w=fmaxf(v.w,0.f);}
            float* d=Xw+i*132+lane*4;
            d[0]=v.x;d[1]=v.y;d[2]=v.z;d[3]=v.w;
        }
        __syncwarp();

        float c[16][4];
        #pragma unroll
        for(int nf=0;nf<16;nf++){c[nf][0]=0.f;c[nf][1]=0.f;c[nf][2]=0.f;c[nf][3]=0.f;}

        #pragma unroll 1
        for(int ks=0;ks<8;ks++){
            int k0=ks*16,kb=ks*8;
            float2 xa=*(const float2*)(Xw+g*132+k0+2*t);
            float2 xb=*(const float2*)(Xw+(g+8)*132+k0+2*t);
            float2 xc=*(const float2*)(Xw+g*132+k0+8+2*t);
            float2 xd=*(const float2*)(Xw+(g+8)*132+k0+8+2*t);
            uint32_t ahi[4],alo[4];
            split2(xa.x,xa.y,ahi[0],alo[0]);
            split2(xb.x,xb.y,ahi[1],alo[1]);
            split2(xc.x,xc.y,ahi[2],alo[2]);
            split2(xd.x,xd.y,ahi[3],alo[3]);
            #pragma unroll
            for(int nf=0;nf<16;nf++){
                int n0=nf*8;
                uint32_t b0h=Wh[(kb+t)*136+n0+g],b1h=Wh[(kb+t+4)*136+n0+g];
                uint32_t b0l=Wl[(kb+t)*136+n0+g],b1l=Wl[(kb+t+4)*136+n0+g];
                mma16(c[nf],ahi,b0h,b1h);
                mma16(c[nf],alo,b0h,b1h);
                mma16(c[nf],ahi,b0l,b1l);
            }
        }

        int ra=r0+g,rb=r0+g+8;
        float da=(ra<n)?__ldg(dinv+ra):0.f;
        float db=(rb<n)?__ldg(dinv+rb):0.f;
        #pragma unroll
        for(int nf=0;nf<16;nf++){
            int col=nf*8+2*t;
            if(ra<n){
                float v0=c[nf][0]*da,v1=c[nf][1]*da;
                *(float2*)(out+(size_t)ra*128+col)=make_float2(v0,v1);
                *(__half2*)(hh+(size_t)ra*128+col)=__floats2half2_rn(v0,v1);
            }
            if(rb<n){
                float v0=c[nf][2]*db,v1=c[nf][3]*db;
                *(float2*)(out+(size_t)rb*128+col)=make_float2(v0,v1);
                *(__half2*)(hh+(size_t)rb*128+col)=__floats2half2_rn(v0,v1);
            }
        }
        __syncwarp();
    }
}

__global__ void rsqrt_kernel(float*d1,float*d2,int n){
    int i=blockIdx.x*blockDim.x+threadIdx.x;
    if(i<n){d1[i]=rsqrtf(d1[i]);d2[i]=rsqrtf(d2[i]);}
}

__global__ void scan_block_sums(const int* __restrict__ cnt,int* __restrict__ bsums,int n){
    __shared__ int wsum[32];
    int i=blockIdx.x*1024+threadIdx.x;
    int v=(i<n)?cnt[i]:0;
    #pragma unroll
    for(int o=16;o;o>>=1) v+=__shfl_down_sync(0xffffffffu,v,o);
    if((threadIdx.x&31)==0) wsum[threadIdx.x>>5]=v;
    __syncthreads();
    if(threadIdx.x<32){
        int s=wsum[threadIdx.x];
        #pragma unroll
        for(int o=16;o;o>>=1) s+=__shfl_down_sync(0xffffffffu,s,o);
        if(threadIdx.x==0) bsums[blockIdx.x]=s;
    }
}
__global__ void scan_final(const int* __restrict__ cnt,const int* __restrict__ bsums,
                           int* __restrict__ base,float* __restrict__ d1,
                           float* __restrict__ d2,int* __restrict__ cur,int n){
    __shared__ int wsum[32];
    __shared__ int boff;
    int tid=threadIdx.x;
    if(tid==0) boff=0;
    __syncthreads();
    if(tid<(int)blockIdx.x) atomicAdd(&boff,__ldg(bsums+tid));
    int i=blockIdx.x*1024+tid;
    int v=(i<n)?cnt[i]:0;
    int lane=tid&31,w=tid>>5;
    int incl=v;
    #pragma unroll
    for(int o=1;o<32;o<<=1){int t=__shfl_up_sync(0xffffffffu,incl,o);if(lane>=o)incl+=t;}
    if(lane==31) wsum[w]=incl;
    __syncthreads();
    if(w==0){
        int s=wsum[lane];
        #pragma unroll
        for(int o=1;o<32;o<<=1){int t=__shfl_up_sync(0xffffffffu,s,o);if(lane>=o)s+=t;}
        __syncwarp();
        wsum[lane]=s;
    }
    __syncthreads();
    int prev=(w==0)?0:wsum[w-1];
    if(i<n){
        base[i]=incl-v+prev+boff;
        d1[i]=1.0f; d2[i]=1.0f; cur[i]=0;
    }
}

// ---------------------------------------------------------------------------
// Gather: out[i] = dinv[i]*( h_fp32[i] + sum g[s]*h_fp16[row[s]] )
__global__ void __launch_bounds__(256)
gather_kernel(const float* __restrict__ h,const __half* __restrict__ hh,
              const float* __restrict__ dinv,
              const int* __restrict__ base,const int* __restrict__ cnt,
              const float2* __restrict__ edges,float* __restrict__ out,int n)
{
    int node=blockIdx.x*(blockDim.x>>5)+(threadIdx.x>>5);
    if(node>=n) return;
    int lane=threadIdx.x&31;
    float4 acc=__ldg((const float4*)(h+(size_t)node*128)+lane);
    int s=__ldg(base+node);
    int end=s+__ldg(cnt+node);
    for(;s+4<=end;s+=4){
        float2 e0=__ldg(edges+s),e1=__ldg(edges+s+1),e2=__ldg(edges+s+2),e3=__ldg(edges+s+3);
        int r0=__float_as_int(e0.x),r1=__float_as_int(e1.x),r2=__float_as_int(e2.x),r3=__float_as_int(e3.x);
        uint2 u0=__ldg((const uint2*)(hh+(size_t)r0*128)+lane);
        uint2 u1=__ldg((const uint2*)(hh+(size_t)r1*128)+lane);
        uint2 u2=__ldg((const uint2*)(hh+(size_t)r2*128)+lane);
        uint2 u3=__ldg((const uint2*)(hh+(size_t)r3*128)+lane);
        float4 v0=h4(u0),v1=h4(u1),v2=h4(u2),v3=h4(u3);
        acc.x=fmaf(e0.y,v0.x,acc.x);acc.y=fmaf(e0.y,v0.y,acc.y);acc.z=fmaf(e0.y,v0.z,acc.z);acc.w=fmaf(e0.y,v0.w,acc.w);
        acc.x=fmaf(e1.y,v1.x,acc.x);acc.y=fmaf(e1.y,v1.y,acc.y);acc.z=fmaf(e1.y,v1.z,acc.z);acc.w=fmaf(e1.y,v1.w,acc.w);
        acc.x=fmaf(e2.y,v2.x,acc.x);acc.y=fmaf(e2.y,v2.y,acc.y);acc.z=fmaf(e2.y,v2.z,acc.z);acc.w=fmaf(e2.y,v2.w,acc.w);
        acc.x=fmaf(e3.y,v3.x,acc.x);acc.y=fmaf(e3.y,v3.y,acc.y);acc.z=fmaf(e3.y,v3.z,acc.z);acc.w=fmaf(e3.y,v3.w,acc.w);
    }
    for(;s<end;s++){
        float2 e0=__ldg(edges+s);
        int r0=__float_as_int(e0.x);
        float4 v0=h4(__ldg((const uint2*)(hh+(size_t)r0*128)+lane));
        acc.x=fmaf(e0.y,v0.x,acc.x);acc.y=fmaf(e0.y,v0.y,acc.y);acc.z=fmaf(e0.y,v0.z,acc.z);acc.w=fmaf(e0.y,v0.w,acc.w);
    }
    float di=__ldg(dinv+node);
    acc.x*=di;acc.y*=di;acc.z*=di;acc.w*=di;
    ((float4*)(out+(size_t)node*128))[lane]=acc;
}

extern "C" void kernel_launch(void* const* d_in,const int* in_sizes,int n_in,
                              void* d_out,int out_size)
{
    const float* x=(const float*)d_in[0];
    const int*   ei=(const int*)d_in[1];
    const float* ea=(const float*)d_in[2];
    const float* W1=(const float*)d_in[3];
    const float* m1w1=(const float*)d_in[4];
    const float* m1b1=(const float*)d_in[5];
    const float* m1w2=(const float*)d_in[6];
    const float* m1b2=(const float*)d_in[7];
    const float* W2=(const float*)d_in[8];
    const float* m2w1=(const float*)d_in[9];
    const float* m2b1=(const float*)d_in[10];
    const float* m2w2=(const float*)d_in[11];
    const float* m2b2=(const float*)d_in[12];
    float* out=(float*)d_out;

    int n=in_sizes[0]/128;
    int E=in_sizes[1]/2;
    const int* rows=ei;
    const int* cols=ei+E;
    int nblk=(n+1023)/1024;

    float *ph,*pagg,*pd1,*pd2;
    __half* phh;
    float2 *pe1,*pe2;
    int *pcnt,*pcur,*pbase,*pbsums;
    cudaGetSymbolAddress((void**)&ph,g_h);
    cudaGetSymbolAddress((void**)&phh,g_hh);
    cudaGetSymbolAddress((void**)&pagg,g_agg);
    cudaGetSymbolAddress((void**)&pd1,g_d1);
    cudaGetSymbolAddress((void**)&pd2,g_d2);
    cudaGetSymbolAddress((void**)&pcnt,g_cnt);
    cudaGetSymbolAddress((void**)&pcur,g_cur);
    cudaGetSymbolAddress((void**)&pbase,g_base);
    cudaGetSymbolAddress((void**)&pbsums,g_bsums);
    cudaGetSymbolAddress((void**)&pe1,g_e1);
    cudaGetSymbolAddress((void**)&pe2,g_e2);

    const int GATE_SMEM=4864*4;                  // 19456 B
    const int GEMM_SMEM=(17408+8*16*132)*4;      // 137216 B
    cudaFuncSetAttribute(gate_mma_kernel,cudaFuncAttributeMaxDynamicSharedMemorySize,GATE_SMEM);
    cudaFuncSetAttribute(gemm_mma_kernel,cudaFuncAttributeMaxDynamicSharedMemorySize,GEMM_SMEM);

    zero_cnt_kernel<<<(n+255)/256,256>>>(pcnt,n);
    hist_kernel<<<(E+255)/256,256>>>(cols,pcnt,E);
    scan_block_sums<<<nblk,1024>>>(pcnt,pbsums,n);
    scan_final<<<nblk,1024>>>(pcnt,pbsums,pbase,pd1,pd2,pcur,n);

    gate_mma_kernel<<<296,256,GATE_SMEM>>>(ea,m1w1,m1b1,m1w2,m1b2,m2w1,m2b1,m2w2,m2b2,
                                           rows,cols,pbase,pcur,pe1,pe2,pd1,pd2,E);
    rsqrt_kernel<<<(n+255)/256,256>>>(pd1,pd2,n);

    gemm_mma_kernel<<<148,256,GEMM_SMEM>>>(x,W1,pd1,ph,phh,n,0);
    gather_kernel<<<(n+7)/8,256>>>(ph,phh,pd1,pbase,pcnt,pe1,pagg,n);

    gemm_mma_kernel<<<148,256,GEMM_SMEM>>>(pagg,W2,pd2,ph,phh,n,1);
    gather_kernel<<<(n+7)/8,256>>>(ph,phh,pd2,pbase,pcnt,pe2,out,n);
}

// round 15
// speedup vs baseline: 2.0355x; 1.0822x over previous
#include <cuda_runtime.h>
#include <cuda_bf16.h>
#include <cuda_fp16.h>
#include <math.h>
#include <cstdint>

#define MAXN 100000
#define MAXE 1600000
#define NBLK 98

// bf16 m16n8k16 mma (sm_80+ PTX)
__device__ __forceinline__ void mma16(float* c,const uint32_t* a,uint32_t b0,uint32_t b1){
    asm volatile("mma.sync.aligned.m16n8k16.row.col.f32.bf16.bf16.f32 "
                 "{%0,%1,%2,%3},{%4,%5,%6,%7},{%8,%9},{%0,%1,%2,%3};"
        :"+f"(c[0]),"+f"(c[1]),"+f"(c[2]),"+f"(c[3])
        :"r"(a[0]),"r"(a[1]),"r"(a[2]),"r"(a[3]),"r"(b0),"r"(b1));
}
// packed split: (x0,x1) -> bf16x2 hi + bf16x2 residual
__device__ __forceinline__ void split2(float x0,float x1,uint32_t&hi,uint32_t&lo){
    __nv_bfloat162 h=__floats2bfloat162_rn(x0,x1);
    hi=reinterpret_cast<uint32_t&>(h);
    float2 f=__bfloat1622float2(h);
    __nv_bfloat162 l=__floats2bfloat162_rn(x0-f.x,x1-f.y);
    lo=reinterpret_cast<uint32_t&>(l);
}
// unpack 4 halves (uint2) -> float4
__device__ __forceinline__ float4 h4(uint2 u){
    __half2 a=*reinterpret_cast<__half2*>(&u.x);
    __half2 b=*reinterpret_cast<__half2*>(&u.y);
    float2 fa=__half22float2(a),fb=__half22float2(b);
    return make_float4(fa.x,fa.y,fb.x,fb.y);
}

__device__ float  g_h[(size_t)MAXN*128];    // h' fp32 (self term + gemm2 input)
__device__ __half g_hh[(size_t)MAXN*128];   // h' fp16 shadow (neighbor gathers)
__device__ float  g_agg[(size_t)MAXN*128];
__device__ float  g_d1[MAXN];               // raw weighted degree (layer 1)
__device__ float  g_d2[MAXN];               // raw weighted degree (layer 2)
__device__ int    g_cnt[MAXN];
__device__ int    g_cur[MAXN];
__device__ int    g_base[MAXN];
__device__ int    g_bsums[NBLK+1];
__device__ float2 g_e1[MAXE];               // CSR slot: {row(bits), g1}
__device__ float2 g_e2[MAXE];               // CSR slot: {row(bits), g2}

__global__ void zero_cnt_kernel(int*cnt,int n){
    int i=blockIdx.x*blockDim.x+threadIdx.x;
    if(i<n) cnt[i]=0;
}
__global__ void hist_kernel(const int* __restrict__ cols,int* __restrict__ cnt,int E){
    int e=blockIdx.x*blockDim.x+threadIdx.x;
    if(e<E) atomicAdd(cnt+__ldg(cols+e),1);
}

// ---------------------------------------------------------------------------
// Gate: bf16 3-term split MMA. Task = 32 edges (2 m-tiles) for occupancy.
__global__ void __launch_bounds__(256) gate_mma_kernel(
    const float* __restrict__ ea,
    const float* __restrict__ m1w1,const float* __restrict__ m1b1,
    const float* __restrict__ m1w2,const float* __restrict__ m1b2,
    const float* __restrict__ m2w1,const float* __restrict__ m2b1,
    const float* __restrict__ m2w2,const float* __restrict__ m2b2,
    const int* __restrict__ rows,const int* __restrict__ cols,
    const int* __restrict__ base,int* __restrict__ cur,
    float2* __restrict__ e1,float2* __restrict__ e2,
    float* __restrict__ deg1,float* __restrict__ deg2,int E)
{
    extern __shared__ float ds[];
    uint32_t* dsu=(uint32_t*)ds;
    float* biasp=ds+4352;
    float* w2p  =ds+4608;
    int tid=threadIdx.x;

    for(int idx=tid;idx<2048;idx+=256){
        int layer=idx>>10,rem=idx&1023,k2=rem>>7,n=rem&127;
        const float* W=layer?m2w1:m1w1;
        float w0=__ldg(W+(2*k2)*128+n),w1=__ldg(W+(2*k2+1)*128+n);
        uint32_t hi,lo; split2(w0,w1,hi,lo);
        dsu[layer*2176+k2*136+n]=hi;
        dsu[layer*2176+1088+k2*136+n]=lo;
    }
    if(tid<256){
        biasp[tid]=(tid<128)?__ldg(m1b1+tid):__ldg(m2b1+tid-128);
        w2p[tid]  =(tid<128)?__ldg(m1w2+tid):__ldg(m2w2+tid-128);
    }
    __syncthreads();

    int lane=tid&31,g=lane>>2,t=lane&3;
    int w=blockIdx.x*(blockDim.x>>5)+(tid>>5);
    int nwarps=gridDim.x*(blockDim.x>>5);
    int ntask=(E+31)>>5;
    float b2v[2]={__ldg(m1b2),__ldg(m2b2)};

    for(int task=w;task<ntask;task+=nwarps){
        int e0=task*32;
        uint32_t Ahi[2][4],Alo[2][4];
        #pragma unroll
        for(int mt=0;mt<2;mt++){
            int r1=e0+mt*16+g,r2=r1+8;
            float2 z=make_float2(0.f,0.f);
            float2 v1a=(r1<E)?*(const float2*)(ea+(size_t)r1*16+2*t):z;
            float2 v1b=(r1<E)?*(const float2*)(ea+(size_t)r1*16+8+2*t):z;
            float2 v2a=(r2<E)?*(const float2*)(ea+(size_t)r2*16+2*t):z;
            float2 v2b=(r2<E)?*(const float2*)(ea+(size_t)r2*16+8+2*t):z;
            split2(v1a.x,v1a.y,Ahi[mt][0],Alo[mt][0]);
            split2(v2a.x,v2a.y,Ahi[mt][1],Alo[mt][1]);
            split2(v1b.x,v1b.y,Ahi[mt][2],Alo[mt][2]);
            split2(v2b.x,v2b.y,Ahi[mt][3],Alo[mt][3]);
        }
        int slotA[2]={-1,-1},slotB[2]={-1,-1};
        #pragma unroll
        for(int layer=0;layer<2;layer++){
            const uint32_t* Bh=dsu+layer*2176;
            const uint32_t* Bl=Bh+1088;
            const float* biasl=biasp+layer*128;
            const float* w2l=w2p+layer*128;
            float p0[2]={0,0},p1[2]={0,0};
            #pragma unroll 2
            for(int nt=0;nt<16;nt++){
                int n0=nt*8;
                float bA=biasl[n0+2*t],bB=biasl[n0+2*t+1];
                float c[2][4];
                #pragma unroll
                for(int mt=0;mt<2;mt++){c[mt][0]=bA;c[mt][1]=bB;c[mt][2]=bA;c[mt][3]=bB;}
                uint32_t b0h=Bh[t*136+n0+g],b1h=Bh[(t+4)*136+n0+g];
                uint32_t b0l=Bl[t*136+n0+g],b1l=Bl[(t+4)*136+n0+g];
                #pragma unroll
                for(int mt=0;mt<2;mt++){
                    mma16(c[mt],Ahi[mt],b0h,b1h);
                    mma16(c[mt],Alo[mt],b0h,b1h);
                    mma16(c[mt],Ahi[mt],b0l,b1l);
                }
                float wA=w2l[n0+2*t],wB=w2l[n0+2*t+1];
                #pragma unroll
                for(int mt=0;mt<2;mt++){
                    p0[mt]+=fmaxf(c[mt][0],0.f)*wA+fmaxf(c[mt][1],0.f)*wB;
                    p1[mt]+=fmaxf(c[mt][2],0.f)*wA+fmaxf(c[mt][3],0.f)*wB;
                }
            }
            #pragma unroll
            for(int mt=0;mt<2;mt++){
                p0[mt]+=__shfl_xor_sync(0xffffffffu,p0[mt],1);
                p0[mt]+=__shfl_xor_sync(0xffffffffu,p0[mt],2);
                p1[mt]+=__shfl_xor_sync(0xffffffffu,p1[mt],1);
                p1[mt]+=__shfl_xor_sync(0xffffffffu,p1[mt],2);
            }
            if(t==0){
                float b2=b2v[layer];
                #pragma unroll
                for(int mt=0;mt<2;mt++){
                    int e=e0+mt*16+g,e2i=e+8;
                    if(layer==0){
                        if(e<E){
                            float gg=1.0f/(1.0f+expf(-(p0[mt]+b2)));
                            int c_=__ldg(cols+e),r_=__ldg(rows+e);
                            int slot=__ldg(base+c_)+atomicAdd(cur+c_,1);
                            slotA[mt]=slot;
                            e1[slot]=make_float2(__int_as_float(r_),gg);
                            atomicAdd(deg1+c_,gg);
                        }
                        if(e2i<E){
                            float gg=1.0f/(1.0f+expf(-(p1[mt]+b2)));
                            int c_=__ldg(cols+e2i),r_=__ldg(rows+e2i);
                            int slot=__ldg(base+c_)+atomicAdd(cur+c_,1);
                            slotB[mt]=slot;
                            e1[slot]=make_float2(__int_as_float(r_),gg);
                            atomicAdd(deg1+c_,gg);
                        }
                    }else{
                        if(slotA[mt]>=0){
                            float gg=1.0f/(1.0f+expf(-(p0[mt]+b2)));
                            int c_=__ldg(cols+e),r_=__ldg(rows+e);
                            e2[slotA[mt]]=make_float2(__int_as_float(r_),gg);
                            atomicAdd(deg2+c_,gg);
                        }
                        if(slotB[mt]>=0){
                            float gg=1.0f/(1.0f+expf(-(p1[mt]+b2)));
                            int c_=__ldg(cols+e2i),r_=__ldg(rows+e2i);
                            e2[slotB[mt]]=make_float2(__int_as_float(r_),gg);
                            atomicAdd(deg2+c_,gg);
                        }
                    }
                }
            }
        }
    }
}

// ---------------------------------------------------------------------------
// Dense GEMM: bf16 3-term split; epilogue scales by rsqrt(deg[r]), writes fp32
// h and fp16 shadow.
__global__ void __launch_bounds__(256) gemm_mma_kernel(
    const float* __restrict__ X,const float* __restrict__ W,
    const float* __restrict__ deg,
    float* __restrict__ out,__half* __restrict__ hh,int n,int relu_in)
{
    extern __shared__ float sm[];
    uint32_t* Wh=(uint32_t*)sm;
    uint32_t* Wl=Wh+8704;
    float* Xs=sm+17408;
    int tid=threadIdx.x,wid=tid>>5,lane=tid&31;
    int g=lane>>2,t=lane&3;

    for(int idx=tid;idx<8192;idx+=256){
        int k2=idx>>7,nn=idx&127;
        float w0=__ldg(W+(2*k2)*128+nn),w1=__ldg(W+(2*k2+1)*128+nn);
        uint32_t hi,lo; split2(w0,w1,hi,lo);
        Wh[k2*136+nn]=hi; Wl[k2*136+nn]=lo;
    }
    __syncthreads();

    float* Xw=Xs+wid*(16*132);
    int ntiles=(n+127)>>7;
    for(int tile=blockIdx.x;tile<ntiles;tile+=gridDim.x){
        int r0=tile*128+wid*16;
        #pragma unroll 4
        for(int i=0;i<16;i++){
            int r=r0+i;
            float4 v=make_float4(0.f,0.f,0.f,0.f);
            if(r<n) v=__ldg((const float4*)(X+(size_t)r*128)+lane);
            if(relu_in){v.x=fmaxf(v.x,0.f);v.y=fmaxf(v.y,0.f);v.z=fmaxf(v.z,0.f);v.w=fmaxf(v.w,0.f);}
            float* d=Xw+i*132+lane*4;
            d[0]=v.x;d[1]=v.y;d[2]=v.z;d[3]=v.w;
        }
        __syncwarp();

        float c[16][4];
        #pragma unroll
        for(int nf=0;nf<16;nf++){c[nf][0]=0.f;c[nf][1]=0.f;c[nf][2]=0.f;c[nf][3]=0.f;}

        #pragma unroll 1
        for(int ks=0;ks<8;ks++){
            int k0=ks*16,kb=ks*8;
            float2 xa=*(const float2*)(Xw+g*132+k0+2*t);
            float2 xb=*(const float2*)(Xw+(g+8)*132+k0+2*t);
            float2 xc=*(const float2*)(Xw+g*132+k0+8+2*t);
            float2 xd=*(const float2*)(Xw+(g+8)*132+k0+8+2*t);
            uint32_t ahi[4],alo[4];
            split2(xa.x,xa.y,ahi[0],alo[0]);
            split2(xb.x,xb.y,ahi[1],alo[1]);
            split2(xc.x,xc.y,ahi[2],alo[2]);
            split2(xd.x,xd.y,ahi[3],alo[3]);
            #pragma unroll
            for(int nf=0;nf<16;nf++){
                int n0=nf*8;
                uint32_t b0h=Wh[(kb+t)*136+n0+g],b1h=Wh[(kb+t+4)*136+n0+g];
                uint32_t b0l=Wl[(kb+t)*136+n0+g],b1l=Wl[(kb+t+4)*136+n0+g];
                mma16(c[nf],ahi,b0h,b1h);
                mma16(c[nf],alo,b0h,b1h);
                mma16(c[nf],ahi,b0l,b1l);
            }
        }

        int ra=r0+g,rb=r0+g+8;
        float da=(ra<n)?rsqrtf(__ldg(deg+ra)):0.f;
        float db=(rb<n)?rsqrtf(__ldg(deg+rb)):0.f;
        #pragma unroll
        for(int nf=0;nf<16;nf++){
            int col=nf*8+2*t;
            if(ra<n){
                float v0=c[nf][0]*da,v1=c[nf][1]*da;
                *(float2*)(out+(size_t)ra*128+col)=make_float2(v0,v1);
                *(__half2*)(hh+(size_t)ra*128+col)=__floats2half2_rn(v0,v1);
            }
            if(rb<n){
                float v0=c[nf][2]*db,v1=c[nf][3]*db;
                *(float2*)(out+(size_t)rb*128+col)=make_float2(v0,v1);
                *(__half2*)(hh+(size_t)rb*128+col)=__floats2half2_rn(v0,v1);
            }
        }
        __syncwarp();
    }
}

__global__ void scan_block_sums(const int* __restrict__ cnt,int* __restrict__ bsums,int n){
    __shared__ int wsum[32];
    int i=blockIdx.x*1024+threadIdx.x;
    int v=(i<n)?cnt[i]:0;
    #pragma unroll
    for(int o=16;o;o>>=1) v+=__shfl_down_sync(0xffffffffu,v,o);
    if((threadIdx.x&31)==0) wsum[threadIdx.x>>5]=v;
    __syncthreads();
    if(threadIdx.x<32){
        int s=wsum[threadIdx.x];
        #pragma unroll
        for(int o=16;o;o>>=1) s+=__shfl_down_sync(0xffffffffu,s,o);
        if(threadIdx.x==0) bsums[blockIdx.x]=s;
    }
}
__global__ void scan_final(const int* __restrict__ cnt,const int* __restrict__ bsums,
                           int* __restrict__ base,float* __restrict__ d1,
                           float* __restrict__ d2,int* __restrict__ cur,int n){
    __shared__ int wsum[32];
    __shared__ int boff;
    int tid=threadIdx.x;
    if(tid==0) boff=0;
    __syncthreads();
    if(tid<(int)blockIdx.x) atomicAdd(&boff,__ldg(bsums+tid));
    int i=blockIdx.x*1024+tid;
    int v=(i<n)?cnt[i]:0;
    int lane=tid&31,w=tid>>5;
    int incl=v;
    #pragma unroll
    for(int o=1;o<32;o<<=1){int t=__shfl_up_sync(0xffffffffu,incl,o);if(lane>=o)incl+=t;}
    if(lane==31) wsum[w]=incl;
    __syncthreads();
    if(w==0){
        int s=wsum[lane];
        #pragma unroll
        for(int o=1;o<32;o<<=1){int t=__shfl_up_sync(0xffffffffu,s,o);if(lane>=o)s+=t;}
        __syncwarp();
        wsum[lane]=s;
    }
    __syncthreads();
    int prev=(w==0)?0:wsum[w-1];
    if(i<n){
        base[i]=incl-v+prev+boff;
        d1[i]=1.0f; d2[i]=1.0f; cur[i]=0;
    }
}

// ---------------------------------------------------------------------------
// Gather: out[i] = rsqrt(deg[i])*( h_fp32[i] + sum g[s]*h_fp16[row[s]] )
__global__ void __launch_bounds__(256)
gather_kernel(const float* __restrict__ h,const __half* __restrict__ hh,
              const float* __restrict__ deg,
              const int* __restrict__ base,const int* __restrict__ cnt,
              const float2* __restrict__ edges,float* __restrict__ out,int n)
{
    int node=blockIdx.x*(blockDim.x>>5)+(threadIdx.x>>5);
    if(node>=n) return;
    int lane=threadIdx.x&31;
    float4 acc=__ldg((const float4*)(h+(size_t)node*128)+lane);
    int s=__ldg(base+node);
    int end=s+__ldg(cnt+node);
    for(;s+4<=end;s+=4){
        float2 e0=__ldg(edges+s),e1=__ldg(edges+s+1),e2=__ldg(edges+s+2),e3=__ldg(edges+s+3);
        int r0=__float_as_int(e0.x),r1=__float_as_int(e1.x),r2=__float_as_int(e2.x),r3=__float_as_int(e3.x);
        uint2 u0=__ldg((const uint2*)(hh+(size_t)r0*128)+lane);
        uint2 u1=__ldg((const uint2*)(hh+(size_t)r1*128)+lane);
        uint2 u2=__ldg((const uint2*)(hh+(size_t)r2*128)+lane);
        uint2 u3=__ldg((const uint2*)(hh+(size_t)r3*128)+lane);
        float4 v0=h4(u0),v1=h4(u1),v2=h4(u2),v3=h4(u3);
        acc.x=fmaf(e0.y,v0.x,acc.x);acc.y=fmaf(e0.y,v0.y,acc.y);acc.z=fmaf(e0.y,v0.z,acc.z);acc.w=fmaf(e0.y,v0.w,acc.w);
        acc.x=fmaf(e1.y,v1.x,acc.x);acc.y=fmaf(e1.y,v1.y,acc.y);acc.z=fmaf(e1.y,v1.z,acc.z);acc.w=fmaf(e1.y,v1.w,acc.w);
        acc.x=fmaf(e2.y,v2.x,acc.x);acc.y=fmaf(e2.y,v2.y,acc.y);acc.z=fmaf(e2.y,v2.z,acc.z);acc.w=fmaf(e2.y,v2.w,acc.w);
        acc.x=fmaf(e3.y,v3.x,acc.x);acc.y=fmaf(e3.y,v3.y,acc.y);acc.z=fmaf(e3.y,v3.z,acc.z);acc.w=fmaf(e3.y,v3.w,acc.w);
    }
    for(;s<end;s++){
        float2 e0=__ldg(edges+s);
        int r0=__float_as_int(e0.x);
        float4 v0=h4(__ldg((const uint2*)(hh+(size_t)r0*128)+lane));
        acc.x=fmaf(e0.y,v0.x,acc.x);acc.y=fmaf(e0.y,v0.y,acc.y);acc.z=fmaf(e0.y,v0.z,acc.z);acc.w=fmaf(e0.y,v0.w,acc.w);
    }
    float di=rsqrtf(__ldg(deg+node));
    acc.x*=di;acc.y*=di;acc.z*=di;acc.w*=di;
    ((float4*)(out+(size_t)node*128))[lane]=acc;
}

extern "C" void kernel_launch(void* const* d_in,const int* in_sizes,int n_in,
                              void* d_out,int out_size)
{
    const float* x=(const float*)d_in[0];
    const int*   ei=(const int*)d_in[1];
    const float* ea=(const float*)d_in[2];
    const float* W1=(const float*)d_in[3];
    const float* m1w1=(const float*)d_in[4];
    const float* m1b1=(const float*)d_in[5];
    const float* m1w2=(const float*)d_in[6];
    const float* m1b2=(const float*)d_in[7];
    const float* W2=(const float*)d_in[8];
    const float* m2w1=(const float*)d_in[9];
    const float* m2b1=(const float*)d_in[10];
    const float* m2w2=(const float*)d_in[11];
    const float* m2b2=(const float*)d_in[12];
    float* out=(float*)d_out;

    int n=in_sizes[0]/128;
    int E=in_sizes[1]/2;
    const int* rows=ei;
    const int* cols=ei+E;
    int nblk=(n+1023)/1024;

    float *ph,*pagg,*pd1,*pd2;
    __half* phh;
    float2 *pe1,*pe2;
    int *pcnt,*pcur,*pbase,*pbsums;
    cudaGetSymbolAddress((void**)&ph,g_h);
    cudaGetSymbolAddress((void**)&phh,g_hh);
    cudaGetSymbolAddress((void**)&pagg,g_agg);
    cudaGetSymbolAddress((void**)&pd1,g_d1);
    cudaGetSymbolAddress((void**)&pd2,g_d2);
    cudaGetSymbolAddress((void**)&pcnt,g_cnt);
    cudaGetSymbolAddress((void**)&pcur,g_cur);
    cudaGetSymbolAddress((void**)&pbase,g_base);
    cudaGetSymbolAddress((void**)&pbsums,g_bsums);
    cudaGetSymbolAddress((void**)&pe1,g_e1);
    cudaGetSymbolAddress((void**)&pe2,g_e2);

    const int GATE_SMEM=4864*4;                  // 19456 B
    const int GEMM_SMEM=(17408+8*16*132)*4;      // 137216 B
    cudaFuncSetAttribute(gate_mma_kernel,cudaFuncAttributeMaxDynamicSharedMemorySize,GATE_SMEM);
    cudaFuncSetAttribute(gemm_mma_kernel,cudaFuncAttributeMaxDynamicSharedMemorySize,GEMM_SMEM);

    zero_cnt_kernel<<<(n+255)/256,256>>>(pcnt,n);
    hist_kernel<<<(E+255)/256,256>>>(cols,pcnt,E);
    scan_block_sums<<<nblk,1024>>>(pcnt,pbsums,n);
    scan_final<<<nblk,1024>>>(pcnt,pbsums,pbase,pd1,pd2,pcur,n);

    gate_mma_kernel<<<592,256,GATE_SMEM>>>(ea,m1w1,m1b1,m1w2,m1b2,m2w1,m2b1,m2w2,m2b2,
                                           rows,cols,pbase,pcur,pe1,pe2,pd1,pd2,E);

    gemm_mma_kernel<<<148,256,GEMM_SMEM>>>(x,W1,pd1,ph,phh,n,0);
    gather_kernel<<<(n+7)/8,256>>>(ph,phh,pd1,pbase,pcnt,pe1,pagg,n);

    gemm_mma_kernel<<<148,256,GEMM_SMEM>>>(pagg,W2,pd2,ph,phh,n,1);
    gather_kernel<<<(n+7)/8,256>>>(ph,phh,pd2,pbase,pcnt,pe2,out,n);
}

// round 16
// speedup vs baseline: 2.3517x; 1.1553x over previous
#include <cuda_runtime.h>
#include <cuda_bf16.h>
#include <cuda_fp16.h>
#include <math.h>
#include <cstdint>

#define MAXN 100000
#define MAXE 1600000
#define NBLK 98

// bf16 m16n8k16 mma (sm_80+ PTX)
__device__ __forceinline__ void mma16(float* c,const uint32_t* a,uint32_t b0,uint32_t b1){
    asm volatile("mma.sync.aligned.m16n8k16.row.col.f32.bf16.bf16.f32 "
                 "{%0,%1,%2,%3},{%4,%5,%6,%7},{%8,%9},{%0,%1,%2,%3};"
        :"+f"(c[0]),"+f"(c[1]),"+f"(c[2]),"+f"(c[3])
        :"r"(a[0]),"r"(a[1]),"r"(a[2]),"r"(a[3]),"r"(b0),"r"(b1));
}
// packed split: (x0,x1) -> bf16x2 hi + bf16x2 residual
__device__ __forceinline__ void split2(float x0,float x1,uint32_t&hi,uint32_t&lo){
    __nv_bfloat162 h=__floats2bfloat162_rn(x0,x1);
    hi=reinterpret_cast<uint32_t&>(h);
    float2 f=__bfloat1622float2(h);
    __nv_bfloat162 l=__floats2bfloat162_rn(x0-f.x,x1-f.y);
    lo=reinterpret_cast<uint32_t&>(l);
}
// unpack 4 halves (uint2) -> float4
__device__ __forceinline__ float4 h4(uint2 u){
    __half2 a=*reinterpret_cast<__half2*>(&u.x);
    __half2 b=*reinterpret_cast<__half2*>(&u.y);
    float2 fa=__half22float2(a),fb=__half22float2(b);
    return make_float4(fa.x,fa.y,fb.x,fb.y);
}

__device__ __half g_hh[(size_t)MAXN*128];   // h' fp16 (only h representation)
__device__ float  g_agg[(size_t)MAXN*128];
__device__ float  g_d1[MAXN];               // raw weighted degree (layer 1)
__device__ float  g_d2[MAXN];               // raw weighted degree (layer 2)
__device__ int    g_cnt[MAXN];
__device__ int    g_cur[MAXN];
__device__ int    g_base[MAXN];
__device__ int    g_bsums[NBLK+1];
__device__ float2 g_e1[MAXE];               // CSR slot: {row(bits), g1}
__device__ float2 g_e2[MAXE];               // CSR slot: {row(bits), g2}

__global__ void zero_cnt_kernel(int*cnt,int n){
    int i=blockIdx.x*blockDim.x+threadIdx.x;
    if(i<n) cnt[i]=0;
}
__global__ void hist_kernel(const int* __restrict__ cols,int* __restrict__ cnt,int E){
    int e=blockIdx.x*blockDim.x+threadIdx.x;
    if(e<E) atomicAdd(cnt+__ldg(cols+e),1);
}

// ---------------------------------------------------------------------------
// Gate: bf16 3-term split MMA. Task = 32 edges (2 m-tiles) for occupancy.
__global__ void __launch_bounds__(256) gate_mma_kernel(
    const float* __restrict__ ea,
    const float* __restrict__ m1w1,const float* __restrict__ m1b1,
    const float* __restrict__ m1w2,const float* __restrict__ m1b2,
    const float* __restrict__ m2w1,const float* __restrict__ m2b1,
    const float* __restrict__ m2w2,const float* __restrict__ m2b2,
    const int* __restrict__ rows,const int* __restrict__ cols,
    const int* __restrict__ base,int* __restrict__ cur,
    float2* __restrict__ e1,float2* __restrict__ e2,
    float* __restrict__ deg1,float* __restrict__ deg2,int E)
{
    extern __shared__ float ds[];
    uint32_t* dsu=(uint32_t*)ds;
    float* biasp=ds+4352;
    float* w2p  =ds+4608;
    int tid=threadIdx.x;

    for(int idx=tid;idx<2048;idx+=256){
        int layer=idx>>10,rem=idx&1023,k2=rem>>7,n=rem&127;
        const float* W=layer?m2w1:m1w1;
        float w0=__ldg(W+(2*k2)*128+n),w1=__ldg(W+(2*k2+1)*128+n);
        uint32_t hi,lo; split2(w0,w1,hi,lo);
        dsu[layer*2176+k2*136+n]=hi;
        dsu[layer*2176+1088+k2*136+n]=lo;
    }
    if(tid<256){
        biasp[tid]=(tid<128)?__ldg(m1b1+tid):__ldg(m2b1+tid-128);
        w2p[tid]  =(tid<128)?__ldg(m1w2+tid):__ldg(m2w2+tid-128);
    }
    __syncthreads();

    int lane=tid&31,g=lane>>2,t=lane&3;
    int w=blockIdx.x*(blockDim.x>>5)+(tid>>5);
    int nwarps=gridDim.x*(blockDim.x>>5);
    int ntask=(E+31)>>5;
    float b2v[2]={__ldg(m1b2),__ldg(m2b2)};

    for(int task=w;task<ntask;task+=nwarps){
        int e0=task*32;
        uint32_t Ahi[2][4],Alo[2][4];
        #pragma unroll
        for(int mt=0;mt<2;mt++){
            int r1=e0+mt*16+g,r2=r1+8;
            float2 z=make_float2(0.f,0.f);
            float2 v1a=(r1<E)?*(const float2*)(ea+(size_t)r1*16+2*t):z;
            float2 v1b=(r1<E)?*(const float2*)(ea+(size_t)r1*16+8+2*t):z;
            float2 v2a=(r2<E)?*(const float2*)(ea+(size_t)r2*16+2*t):z;
            float2 v2b=(r2<E)?*(const float2*)(ea+(size_t)r2*16+8+2*t):z;
            split2(v1a.x,v1a.y,Ahi[mt][0],Alo[mt][0]);
            split2(v2a.x,v2a.y,Ahi[mt][1],Alo[mt][1]);
            split2(v1b.x,v1b.y,Ahi[mt][2],Alo[mt][2]);
            split2(v2b.x,v2b.y,Ahi[mt][3],Alo[mt][3]);
        }
        int slotA[2]={-1,-1},slotB[2]={-1,-1};
        #pragma unroll
        for(int layer=0;layer<2;layer++){
            const uint32_t* Bh=dsu+layer*2176;
            const uint32_t* Bl=Bh+1088;
            const float* biasl=biasp+layer*128;
            const float* w2l=w2p+layer*128;
            float p0[2]={0,0},p1[2]={0,0};
            #pragma unroll 2
            for(int nt=0;nt<16;nt++){
                int n0=nt*8;
                float bA=biasl[n0+2*t],bB=biasl[n0+2*t+1];
                float c[2][4];
                #pragma unroll
                for(int mt=0;mt<2;mt++){c[mt][0]=bA;c[mt][1]=bB;c[mt][2]=bA;c[mt][3]=bB;}
                uint32_t b0h=Bh[t*136+n0+g],b1h=Bh[(t+4)*136+n0+g];
                uint32_t b0l=Bl[t*136+n0+g],b1l=Bl[(t+4)*136+n0+g];
                #pragma unroll
                for(int mt=0;mt<2;mt++){
                    mma16(c[mt],Ahi[mt],b0h,b1h);
                    mma16(c[mt],Alo[mt],b0h,b1h);
                    mma16(c[mt],Ahi[mt],b0l,b1l);
                }
                float wA=w2l[n0+2*t],wB=w2l[n0+2*t+1];
                #pragma unroll
                for(int mt=0;mt<2;mt++){
                    p0[mt]+=fmaxf(c[mt][0],0.f)*wA+fmaxf(c[mt][1],0.f)*wB;
                    p1[mt]+=fmaxf(c[mt][2],0.f)*wA+fmaxf(c[mt][3],0.f)*wB;
                }
            }
            #pragma unroll
            for(int mt=0;mt<2;mt++){
                p0[mt]+=__shfl_xor_sync(0xffffffffu,p0[mt],1);
                p0[mt]+=__shfl_xor_sync(0xffffffffu,p0[mt],2);
                p1[mt]+=__shfl_xor_sync(0xffffffffu,p1[mt],1);
                p1[mt]+=__shfl_xor_sync(0xffffffffu,p1[mt],2);
            }
            if(t==0){
                float b2=b2v[layer];
                #pragma unroll
                for(int mt=0;mt<2;mt++){
                    int e=e0+mt*16+g,e2i=e+8;
                    if(layer==0){
                        if(e<E){
                            float gg=1.0f/(1.0f+expf(-(p0[mt]+b2)));
                            int c_=__ldg(cols+e),r_=__ldg(rows+e);
                            int slot=__ldg(base+c_)+atomicAdd(cur+c_,1);
                            slotA[mt]=slot;
                            e1[slot]=make_float2(__int_as_float(r_),gg);
                            atomicAdd(deg1+c_,gg);
                        }
                        if(e2i<E){
                            float gg=1.0f/(1.0f+expf(-(p1[mt]+b2)));
                            int c_=__ldg(cols+e2i),r_=__ldg(rows+e2i);
                            int slot=__ldg(base+c_)+atomicAdd(cur+c_,1);
                            slotB[mt]=slot;
                            e1[slot]=make_float2(__int_as_float(r_),gg);
                            atomicAdd(deg1+c_,gg);
                        }
                    }else{
                        if(slotA[mt]>=0){
                            float gg=1.0f/(1.0f+expf(-(p0[mt]+b2)));
                            int c_=__ldg(cols+e),r_=__ldg(rows+e);
                            e2[slotA[mt]]=make_float2(__int_as_float(r_),gg);
                            atomicAdd(deg2+c_,gg);
                        }
                        if(slotB[mt]>=0){
                            float gg=1.0f/(1.0f+expf(-(p1[mt]+b2)));
                            int c_=__ldg(cols+e2i),r_=__ldg(rows+e2i);
                            e2[slotB[mt]]=make_float2(__int_as_float(r_),gg);
                            atomicAdd(deg2+c_,gg);
                        }
                    }
                }
            }
        }
    }
}

// ---------------------------------------------------------------------------
// Dense GEMM: bf16 3-term split; 512 threads (16 warps) for latency hiding.
// Epilogue scales by rsqrt(deg[r]) and writes ONLY the fp16 shadow.
__global__ void __launch_bounds__(512) gemm_mma_kernel(
    const float* __restrict__ X,const float* __restrict__ W,
    const float* __restrict__ deg,
    __half* __restrict__ hh,int n,int relu_in)
{
    extern __shared__ float sm[];
    uint32_t* Wh=(uint32_t*)sm;       // 8704 u32
    uint32_t* Wl=Wh+8704;             // 8704 u32
    float* Xs=sm+17408;               // 16 warps * 16*132 floats
    int tid=threadIdx.x,wid=tid>>5,lane=tid&31;
    int g=lane>>2,t=lane&3;

    for(int idx=tid;idx<8192;idx+=512){
        int k2=idx>>7,nn=idx&127;
        float w0=__ldg(W+(2*k2)*128+nn),w1=__ldg(W+(2*k2+1)*128+nn);
        uint32_t hi,lo; split2(w0,w1,hi,lo);
        Wh[k2*136+nn]=hi; Wl[k2*136+nn]=lo;
    }
    __syncthreads();

    float* Xw=Xs+wid*(16*132);
    int ntiles=(n+255)>>8;
    for(int tile=blockIdx.x;tile<ntiles;tile+=gridDim.x){
        int r0=tile*256+wid*16;
        #pragma unroll 4
        for(int i=0;i<16;i++){
            int r=r0+i;
            float4 v=make_float4(0.f,0.f,0.f,0.f);
            if(r<n) v=__ldg((const float4*)(X+(size_t)r*128)+lane);
            if(relu_in){v.x=fmaxf(v.x,0.f);v.y=fmaxf(v.y,0.f);v.z=fmaxf(v.z,0.f);v.w=fmaxf(v.w,0.f);}
            float* d=Xw+i*132+lane*4;
            d[0]=v.x;d[1]=v.y;d[2]=v.z;d[3]=v.w;
        }
        __syncwarp();

        float c[16][4];
        #pragma unroll
        for(int nf=0;nf<16;nf++){c[nf][0]=0.f;c[nf][1]=0.f;c[nf][2]=0.f;c[nf][3]=0.f;}

        #pragma unroll 1
        for(int ks=0;ks<8;ks++){
            int k0=ks*16,kb=ks*8;
            float2 xa=*(const float2*)(Xw+g*132+k0+2*t);
            float2 xb=*(const float2*)(Xw+(g+8)*132+k0+2*t);
            float2 xc=*(const float2*)(Xw+g*132+k0+8+2*t);
            float2 xd=*(const float2*)(Xw+(g+8)*132+k0+8+2*t);
            uint32_t ahi[4],alo[4];
            split2(xa.x,xa.y,ahi[0],alo[0]);
            split2(xb.x,xb.y,ahi[1],alo[1]);
            split2(xc.x,xc.y,ahi[2],alo[2]);
            split2(xd.x,xd.y,ahi[3],alo[3]);
            #pragma unroll
            for(int nf=0;nf<16;nf++){
                int n0=nf*8;
                uint32_t b0h=Wh[(kb+t)*136+n0+g],b1h=Wh[(kb+t+4)*136+n0+g];
                uint32_t b0l=Wl[(kb+t)*136+n0+g],b1l=Wl[(kb+t+4)*136+n0+g];
                mma16(c[nf],ahi,b0h,b1h);
                mma16(c[nf],alo,b0h,b1h);
                mma16(c[nf],ahi,b0l,b1l);
            }
        }

        int ra=r0+g,rb=r0+g+8;
        float da=(ra<n)?rsqrtf(__ldg(deg+ra)):0.f;
        float db=(rb<n)?rsqrtf(__ldg(deg+rb)):0.f;
        #pragma unroll
        for(int nf=0;nf<16;nf++){
            int col=nf*8+2*t;
            if(ra<n) *(__half2*)(hh+(size_t)ra*128+col)=__floats2half2_rn(c[nf][0]*da,c[nf][1]*da);
            if(rb<n) *(__half2*)(hh+(size_t)rb*128+col)=__floats2half2_rn(c[nf][2]*db,c[nf][3]*db);
        }
        __syncwarp();
    }
}

__global__ void scan_block_sums(const int* __restrict__ cnt,int* __restrict__ bsums,int n){
    __shared__ int wsum[32];
    int i=blockIdx.x*1024+threadIdx.x;
    int v=(i<n)?cnt[i]:0;
    #pragma unroll
    for(int o=16;o;o>>=1) v+=__shfl_down_sync(0xffffffffu,v,o);
    if((threadIdx.x&31)==0) wsum[threadIdx.x>>5]=v;
    __syncthreads();
    if(threadIdx.x<32){
        int s=wsum[threadIdx.x];
        #pragma unroll
        for(int o=16;o;o>>=1) s+=__shfl_down_sync(0xffffffffu,s,o);
        if(threadIdx.x==0) bsums[blockIdx.x]=s;
    }
}
__global__ void scan_final(const int* __restrict__ cnt,const int* __restrict__ bsums,
                           int* __restrict__ base,float* __restrict__ d1,
                           float* __restrict__ d2,int* __restrict__ cur,int n){
    __shared__ int wsum[32];
    __shared__ int boff;
    int tid=threadIdx.x;
    if(tid==0) boff=0;
    __syncthreads();
    if(tid<(int)blockIdx.x) atomicAdd(&boff,__ldg(bsums+tid));
    int i=blockIdx.x*1024+tid;
    int v=(i<n)?cnt[i]:0;
    int lane=tid&31,w=tid>>5;
    int incl=v;
    #pragma unroll
    for(int o=1;o<32;o<<=1){int t=__shfl_up_sync(0xffffffffu,incl,o);if(lane>=o)incl+=t;}
    if(lane==31) wsum[w]=incl;
    __syncthreads();
    if(w==0){
        int s=wsum[lane];
        #pragma unroll
        for(int o=1;o<32;o<<=1){int t=__shfl_up_sync(0xffffffffu,s,o);if(lane>=o)s+=t;}
        __syncwarp();
        wsum[lane]=s;
    }
    __syncthreads();
    int prev=(w==0)?0:wsum[w-1];
    if(i<n){
        base[i]=incl-v+prev+boff;
        d1[i]=1.0f; d2[i]=1.0f; cur[i]=0;
    }
}

// ---------------------------------------------------------------------------
// Gather: out[i] = rsqrt(deg[i])*( hh[i] + sum g[s]*hh[row[s]] )   (all fp16 h)
__global__ void __launch_bounds__(256)
gather_kernel(const __half* __restrict__ hh,const float* __restrict__ deg,
              const int* __restrict__ base,const int* __restrict__ cnt,
              const float2* __restrict__ edges,float* __restrict__ out,int n)
{
    int node=blockIdx.x*(blockDim.x>>5)+(threadIdx.x>>5);
    if(node>=n) return;
    int lane=threadIdx.x&31;
    float4 acc=h4(__ldg((const uint2*)(hh+(size_t)node*128)+lane));
    int s=__ldg(base+node);
    int end=s+__ldg(cnt+node);
    for(;s+4<=end;s+=4){
        float2 e0=__ldg(edges+s),e1=__ldg(edges+s+1),e2=__ldg(edges+s+2),e3=__ldg(edges+s+3);
        int r0=__float_as_int(e0.x),r1=__float_as_int(e1.x),r2=__float_as_int(e2.x),r3=__float_as_int(e3.x);
        uint2 u0=__ldg((const uint2*)(hh+(size_t)r0*128)+lane);
        uint2 u1=__ldg((const uint2*)(hh+(size_t)r1*128)+lane);
        uint2 u2=__ldg((const uint2*)(hh+(size_t)r2*128)+lane);
        uint2 u3=__ldg((const uint2*)(hh+(size_t)r3*128)+lane);
        float4 v0=h4(u0),v1=h4(u1),v2=h4(u2),v3=h4(u3);
        acc.x=fmaf(e0.y,v0.x,acc.x);acc.y=fmaf(e0.y,v0.y,acc.y);acc.z=fmaf(e0.y,v0.z,acc.z);acc.w=fmaf(e0.y,v0.w,acc.w);
        acc.x=fmaf(e1.y,v1.x,acc.x);acc.y=fmaf(e1.y,v1.y,acc.y);acc.z=fmaf(e1.y,v1.z,acc.z);acc.w=fmaf(e1.y,v1.w,acc.w);
        acc.x=fmaf(e2.y,v2.x,acc.x);acc.y=fmaf(e2.y,v2.y,acc.y);acc.z=fmaf(e2.y,v2.z,acc.z);acc.w=fmaf(e2.y,v2.w,acc.w);
        acc.x=fmaf(e3.y,v3.x,acc.x);acc.y=fmaf(e3.y,v3.y,acc.y);acc.z=fmaf(e3.y,v3.z,acc.z);acc.w=fmaf(e3.y,v3.w,acc.w);
    }
    for(;s<end;s++){
        float2 e0=__ldg(edges+s);
        int r0=__float_as_int(e0.x);
        float4 v0=h4(__ldg((const uint2*)(hh+(size_t)r0*128)+lane));
        acc.x=fmaf(e0.y,v0.x,acc.x);acc.y=fmaf(e0.y,v0.y,acc.y);acc.z=fmaf(e0.y,v0.z,acc.z);acc.w=fmaf(e0.y,v0.w,acc.w);
    }
    float di=rsqrtf(__ldg(deg+node));
    acc.x*=di;acc.y*=di;acc.z*=di;acc.w*=di;
    ((float4*)(out+(size_t)node*128))[lane]=acc;
}

extern "C" void kernel_launch(void* const* d_in,const int* in_sizes,int n_in,
                              void* d_out,int out_size)
{
    const float* x=(const float*)d_in[0];
    const int*   ei=(const int*)d_in[1];
    const float* ea=(const float*)d_in[2];
    const float* W1=(const float*)d_in[3];
    const float* m1w1=(const float*)d_in[4];
    const float* m1b1=(const float*)d_in[5];
    const float* m1w2=(const float*)d_in[6];
    const float* m1b2=(const float*)d_in[7];
    const float* W2=(const float*)d_in[8];
    const float* m2w1=(const float*)d_in[9];
    const float* m2b1=(const float*)d_in[10];
    const float* m2w2=(const float*)d_in[11];
    const float* m2b2=(const float*)d_in[12];
    float* out=(float*)d_out;

    int n=in_sizes[0]/128;
    int E=in_sizes[1]/2;
    const int* rows=ei;
    const int* cols=ei+E;
    int nblk=(n+1023)/1024;

    float *pagg,*pd1,*pd2;
    __half* phh;
    float2 *pe1,*pe2;
    int *pcnt,*pcur,*pbase,*pbsums;
    cudaGetSymbolAddress((void**)&phh,g_hh);
    cudaGetSymbolAddress((void**)&pagg,g_agg);
    cudaGetSymbolAddress((void**)&pd1,g_d1);
    cudaGetSymbolAddress((void**)&pd2,g_d2);
    cudaGetSymbolAddress((void**)&pcnt,g_cnt);
    cudaGetSymbolAddress((void**)&pcur,g_cur);
    cudaGetSymbolAddress((void**)&pbase,g_base);
    cudaGetSymbolAddress((void**)&pbsums,g_bsums);
    cudaGetSymbolAddress((void**)&pe1,g_e1);
    cudaGetSymbolAddress((void**)&pe2,g_e2);

    const int GATE_SMEM=4864*4;                  // 19456 B
    const int GEMM_SMEM=(17408+16*16*132)*4;     // 204800 B
    cudaFuncSetAttribute(gate_mma_kernel,cudaFuncAttributeMaxDynamicSharedMemorySize,GATE_SMEM);
    cudaFuncSetAttribute(gemm_mma_kernel,cudaFuncAttributeMaxDynamicSharedMemorySize,GEMM_SMEM);

    zero_cnt_kernel<<<(n+255)/256,256>>>(pcnt,n);
    hist_kernel<<<(E+255)/256,256>>>(cols,pcnt,E);
    scan_block_sums<<<nblk,1024>>>(pcnt,pbsums,n);
    scan_final<<<nblk,1024>>>(pcnt,pbsums,pbase,pd1,pd2,pcur,n);

    gate_mma_kernel<<<592,256,GATE_SMEM>>>(ea,m1w1,m1b1,m1w2,m1b2,m2w1,m2b1,m2w2,m2b2,
                                           rows,cols,pbase,pcur,pe1,pe2,pd1,pd2,E);

    gemm_mma_kernel<<<148,512,GEMM_SMEM>>>(x,W1,pd1,phh,n,0);
    gather_kernel<<<(n+7)/8,256>>>(phh,pd1,pbase,pcnt,pe1,pagg,n);

    gemm_mma_kernel<<<148,512,GEMM_SMEM>>>(pagg,W2,pd2,phh,n,1);
    gather_kernel<<<(n+7)/8,256>>>(phh,pd2,pbase,pcnt,pe2,out,n);
}